// round 1
// baseline (speedup 1.0000x reference)
#include <cuda_runtime.h>
#include <math.h>

// ---------------- problem constants ----------------
#define NBATCH 4
#define IMG    256
#define C      128
#define ACTPTS 32768            // IMG*IMG/2
#define NPTS   (NBATCH*ACTPTS)  // 131072
#define TD     512
#define ZD     256
#define HID    256              // MULT*C
#define LN_EPS 1e-5f

// ---------------- scratch (device globals; no runtime allocation) ----------------
__device__ float g_h1[(size_t)NPTS * C];     // modulated input to conv (64 MB)
__device__ float g_x [(size_t)NPTS * C];     // x = x_features + conv/norm (64 MB)
__device__ int   g_grid[NBATCH * IMG * IMG]; // (b,y,x) -> point index or -1
__device__ float g_tt1[NBATCH * 2 * C];
__device__ float g_tt2[NBATCH * 2 * C];
__device__ float g_zz1[NBATCH * C];
__device__ float g_zz2[NBATCH * C];

__device__ __forceinline__ float gelu_exact(float x) {
    return 0.5f * x * (1.0f + erff(x * 0.70710678118654752440f));
}

// ---------------- grid build ----------------
__global__ void fill_grid_kernel() {
    int i = blockIdx.x * 256 + threadIdx.x;
    g_grid[i] = -1;
}

__global__ void scatter_grid_kernel(const int* __restrict__ xidx) {
    int n = blockIdx.x * 256 + threadIdx.x;
    int b = xidx[3 * n + 0];
    int y = xidx[3 * n + 1];
    int x = xidx[3 * n + 2];
    g_grid[(b << 16) | (y << 8) | x] = n;
}

// ---------------- per-batch modulation vectors ----------------
// gridDim = (NBATCH, 2): y==0 -> tt1/tt2 (256 threads = 2C outputs)
//                        y==1 -> zz1/zz2 (two chained GEMVs)
__global__ void modvec_kernel(
    const float* __restrict__ t,   const float* __restrict__ z,
    const float* __restrict__ t1w, const float* __restrict__ t1b,
    const float* __restrict__ t2w, const float* __restrict__ t2b,
    const float* __restrict__ z1w1, const float* __restrict__ z1b1,
    const float* __restrict__ z1w2, const float* __restrict__ z1b2,
    const float* __restrict__ z2w1, const float* __restrict__ z2b1,
    const float* __restrict__ z2w2, const float* __restrict__ z2b2)
{
    const int b   = blockIdx.x;
    const int tid = threadIdx.x;

    if (blockIdx.y == 0) {
        __shared__ float gt[TD];
        gt[tid]       = gelu_exact(t[b * TD + tid]);
        gt[tid + 256] = gelu_exact(t[b * TD + tid + 256]);
        __syncthreads();
        float a1 = t1b[tid], a2 = t2b[tid];
        #pragma unroll 8
        for (int k = 0; k < TD; k++) {
            float g = gt[k];
            a1 += g * t1w[k * 256 + tid];
            a2 += g * t2w[k * 256 + tid];
        }
        g_tt1[b * 256 + tid] = a1;
        g_tt2[b * 256 + tid] = a2;
    } else {
        __shared__ float gz[ZD];
        __shared__ float hz[2 * C];
        gz[tid] = z[b * ZD + tid];
        __syncthreads();
        {
            int j = tid & 127;
            const float* w  = (tid < 128) ? z1w1 : z2w1;
            const float* bb = (tid < 128) ? z1b1 : z2b1;
            float a = bb[j];
            #pragma unroll 8
            for (int k = 0; k < ZD; k++) a += gz[k] * w[k * C + j];
            hz[tid] = gelu_exact(a);
        }
        __syncthreads();
        {
            int j = tid & 127;
            const float* w  = (tid < 128) ? z1w2 : z2w2;
            const float* bb = (tid < 128) ? z1b2 : z2b2;
            const float* h  = (tid < 128) ? hz : (hz + C);
            float a = bb[j];
            #pragma unroll 8
            for (int k = 0; k < C; k++) a += h[k] * w[k * C + j];
            if (tid < 128) g_zz1[b * C + j] = a;
            else           g_zz2[b * C + j] = a;
        }
    }
}

// ---------------- stage-1 modulate: LN + t/z modulation -> g_h1 ----------------
__global__ void modulate1_kernel(const float* __restrict__ xf,
                                 const float* __restrict__ lnw,
                                 const float* __restrict__ lnb)
{
    const int warp = threadIdx.x >> 5;
    const int lane = threadIdx.x & 31;
    const int n = blockIdx.x * 8 + warp;
    const int b = n >> 15;   // ACTPTS = 2^15

    float4 v = *(const float4*)(xf + (size_t)n * C + lane * 4);
    float s  = v.x + v.y + v.z + v.w;
    float sq = v.x * v.x + v.y * v.y + v.z * v.z + v.w * v.w;
    #pragma unroll
    for (int o = 16; o; o >>= 1) {
        s  += __shfl_xor_sync(0xffffffffu, s,  o);
        sq += __shfl_xor_sync(0xffffffffu, sq, o);
    }
    float mu = s * (1.0f / C);
    float rs = rsqrtf(sq * (1.0f / C) - mu * mu + LN_EPS);

    float vv[4] = {v.x, v.y, v.z, v.w};
    float o4[4];
    #pragma unroll
    for (int u = 0; u < 4; u++) {
        int c = lane * 4 + u;
        float f = (vv[u] - mu) * rs * lnw[c] + lnb[c];
        f = f * (1.0f + g_tt1[b * 256 + c]) + g_tt1[b * 256 + 128 + c];
        o4[u] = f * (1.0f + g_zz1[b * 128 + c]);
    }
    *(float4*)(g_h1 + (size_t)n * C + lane * 4) = *(float4*)o4;
}

// ---------------- sparse 7x7 conv (gather-GEMM) + /norm + residual -> g_x ----------------
// Block: 64 points x 128 output channels, 256 threads.
// Thread (ty,tx): rows ty*4..+3, cols {tx*4..+3} U {64+tx*4..+3}  (4x8 register tile)
__global__ __launch_bounds__(256) void conv_kernel(
    const float* __restrict__ xf, const float* __restrict__ nrm,
    const int* __restrict__ xidx, const float* __restrict__ convw)
{
    __shared__ float As[32][68];    // [k][row] transposed neighbor chunk (row-dim padded)
    __shared__ float Ws[32][128];   // [k][cout] weight chunk
    __shared__ int   nb[64];
    __shared__ int   sbase[64], sy[64], sx[64];

    const int tid = threadIdx.x;
    const int ty = tid >> 4, tx = tid & 15;
    const int r0 = ty * 4, c0 = tx * 4;
    const int base = blockIdx.x * 64;

    if (tid < 64) {
        int n = base + tid;
        sbase[tid] = xidx[3 * n + 0] << 16;
        sy[tid]    = xidx[3 * n + 1];
        sx[tid]    = xidx[3 * n + 2];
    }

    float acc[4][8];
    #pragma unroll
    for (int i = 0; i < 4; i++)
        #pragma unroll
        for (int j = 0; j < 8; j++) acc[i][j] = 0.0f;

    __syncthreads();

    const int arow = tid >> 3;   // 0..31
    const int aq   = tid & 7;    // 0..7 (float4 slot within 32-float chunk)

    for (int tap = 0; tap < 49; tap++) {
        const int ky = tap / 7 - 3, kx = tap % 7 - 3;
        if (tid < 64) {
            int ny = sy[tid] + ky, nx = sx[tid] + kx;
            int v = -1;
            if ((unsigned)ny < 256u && (unsigned)nx < 256u)
                v = g_grid[sbase[tid] | (ny << 8) | nx];
            nb[tid] = v;
        }
        __syncthreads();

        const float* wt = convw + tap * (C * C);

        for (int kc = 0; kc < 4; kc++) {
            // gather neighbor features, store transposed [k][row]
            {
                int src = nb[arow];
                float4 v = make_float4(0.f, 0.f, 0.f, 0.f);
                if (src >= 0) v = *(const float4*)(g_h1 + (size_t)src * C + kc * 32 + aq * 4);
                As[aq * 4 + 0][arow] = v.x;
                As[aq * 4 + 1][arow] = v.y;
                As[aq * 4 + 2][arow] = v.z;
                As[aq * 4 + 3][arow] = v.w;

                int row2 = arow + 32;
                int src2 = nb[row2];
                float4 v2 = make_float4(0.f, 0.f, 0.f, 0.f);
                if (src2 >= 0) v2 = *(const float4*)(g_h1 + (size_t)src2 * C + kc * 32 + aq * 4);
                As[aq * 4 + 0][row2] = v2.x;
                As[aq * 4 + 1][row2] = v2.y;
                As[aq * 4 + 2][row2] = v2.z;
                As[aq * 4 + 3][row2] = v2.w;
            }
            // load weight chunk [32][128]
            #pragma unroll
            for (int l = 0; l < 4; l++) {
                int li = tid + l * 256;
                int k = li >> 5, q = li & 31;
                *(float4*)&Ws[k][q * 4] = *(const float4*)(wt + (kc * 32 + k) * C + q * 4);
            }
            __syncthreads();

            #pragma unroll 8
            for (int k = 0; k < 32; k++) {
                float4 a  = *(float4*)&As[k][r0];
                float4 bA = *(float4*)&Ws[k][c0];
                float4 bB = *(float4*)&Ws[k][c0 + 64];
                float av[4] = {a.x, a.y, a.z, a.w};
                float bv[8] = {bA.x, bA.y, bA.z, bA.w, bB.x, bB.y, bB.z, bB.w};
                #pragma unroll
                for (int i = 0; i < 4; i++)
                    #pragma unroll
                    for (int j = 0; j < 8; j++)
                        acc[i][j] += av[i] * bv[j];
            }
            __syncthreads();
        }
    }

    // epilogue: x = x_features + conv/norm
    #pragma unroll
    for (int i = 0; i < 4; i++) {
        int n = base + r0 + i;
        float inv = 1.0f / nrm[n];
        float4 x0 = *(const float4*)(xf + (size_t)n * C + c0);
        float4 x1 = *(const float4*)(xf + (size_t)n * C + c0 + 64);
        float4 o0 = make_float4(x0.x + acc[i][0] * inv, x0.y + acc[i][1] * inv,
                                x0.z + acc[i][2] * inv, x0.w + acc[i][3] * inv);
        float4 o1 = make_float4(x1.x + acc[i][4] * inv, x1.y + acc[i][5] * inv,
                                x1.z + acc[i][6] * inv, x1.w + acc[i][7] * inv);
        *(float4*)(g_x + (size_t)n * C + c0)      = o0;
        *(float4*)(g_x + (size_t)n * C + c0 + 64) = o1;
    }
}

// ---------------- stage-2: LN2 + modulation + MLP + residual -> out ----------------
// Block: 32 rows, 256 threads (8 warps x 32 lanes). smem = 16KB + 32KB = 48KB exactly.
__global__ __launch_bounds__(256) void mlp_kernel(
    const float* __restrict__ lnw, const float* __restrict__ lnb,
    const float* __restrict__ w1,  const float* __restrict__ b1,
    const float* __restrict__ w2,  const float* __restrict__ b2,
    float* __restrict__ out)
{
    __shared__ float As[32][128];
    __shared__ float Hs[32][256];

    const int tid  = threadIdx.x;
    const int warp = tid >> 5, lane = tid & 31;
    const int base = blockIdx.x * 32;

    // phase 1: LN + modulation (4 rows per warp)
    #pragma unroll
    for (int rr = 0; rr < 4; rr++) {
        int r = warp * 4 + rr;
        int n = base + r;
        int b = n >> 15;
        float4 v = *(const float4*)(g_x + (size_t)n * C + lane * 4);
        float s  = v.x + v.y + v.z + v.w;
        float sq = v.x * v.x + v.y * v.y + v.z * v.z + v.w * v.w;
        #pragma unroll
        for (int o = 16; o; o >>= 1) {
            s  += __shfl_xor_sync(0xffffffffu, s,  o);
            sq += __shfl_xor_sync(0xffffffffu, sq, o);
        }
        float mu = s * (1.0f / C);
        float rs = rsqrtf(sq * (1.0f / C) - mu * mu + LN_EPS);
        float vv[4] = {v.x, v.y, v.z, v.w};
        float o4[4];
        #pragma unroll
        for (int u = 0; u < 4; u++) {
            int c = lane * 4 + u;
            float f = (vv[u] - mu) * rs * lnw[c] + lnb[c];
            f = f * (1.0f + g_tt2[b * 256 + c]) + g_tt2[b * 256 + 128 + c];
            o4[u] = f * (1.0f + g_zz2[b * 128 + c]);
        }
        *(float4*)&As[r][lane * 4] = *(float4*)o4;
    }
    __syncthreads();

    // phase 2: H = gelu(A @ w1 + b1)   (rows warp*4..+3, cols {lane*4..+3} U {128+lane*4..+3})
    float acc[4][8];
    {
        float4 bA = *(const float4*)(b1 + lane * 4);
        float4 bB = *(const float4*)(b1 + 128 + lane * 4);
        #pragma unroll
        for (int i = 0; i < 4; i++) {
            acc[i][0] = bA.x; acc[i][1] = bA.y; acc[i][2] = bA.z; acc[i][3] = bA.w;
            acc[i][4] = bB.x; acc[i][5] = bB.y; acc[i][6] = bB.z; acc[i][7] = bB.w;
        }
    }
    #pragma unroll 4
    for (int k = 0; k < C; k++) {
        float av[4];
        #pragma unroll
        for (int i = 0; i < 4; i++) av[i] = As[warp * 4 + i][k];
        float4 wA = *(const float4*)(w1 + k * 256 + lane * 4);
        float4 wB = *(const float4*)(w1 + k * 256 + 128 + lane * 4);
        float wv[8] = {wA.x, wA.y, wA.z, wA.w, wB.x, wB.y, wB.z, wB.w};
        #pragma unroll
        for (int i = 0; i < 4; i++)
            #pragma unroll
            for (int j = 0; j < 8; j++)
                acc[i][j] += av[i] * wv[j];
    }
    #pragma unroll
    for (int i = 0; i < 4; i++) {
        int r = warp * 4 + i;
        float4 hA = make_float4(gelu_exact(acc[i][0]), gelu_exact(acc[i][1]),
                                gelu_exact(acc[i][2]), gelu_exact(acc[i][3]));
        float4 hB = make_float4(gelu_exact(acc[i][4]), gelu_exact(acc[i][5]),
                                gelu_exact(acc[i][6]), gelu_exact(acc[i][7]));
        *(float4*)&Hs[r][lane * 4]       = hA;
        *(float4*)&Hs[r][128 + lane * 4] = hB;
    }
    __syncthreads();

    // phase 3: out = x + H @ w2 + b2   (rows warp*4..+3, cols lane*4..+3)
    float acc2[4][4];
    {
        float4 bv = *(const float4*)(b2 + lane * 4);
        #pragma unroll
        for (int i = 0; i < 4; i++) {
            acc2[i][0] = bv.x; acc2[i][1] = bv.y; acc2[i][2] = bv.z; acc2[i][3] = bv.w;
        }
    }
    #pragma unroll 4
    for (int k = 0; k < HID; k++) {
        float4 wv = *(const float4*)(w2 + k * C + lane * 4);
        #pragma unroll
        for (int i = 0; i < 4; i++) {
            float a = Hs[warp * 4 + i][k];
            acc2[i][0] += a * wv.x;
            acc2[i][1] += a * wv.y;
            acc2[i][2] += a * wv.z;
            acc2[i][3] += a * wv.w;
        }
    }
    #pragma unroll
    for (int i = 0; i < 4; i++) {
        int n = base + warp * 4 + i;
        float4 xv = *(const float4*)(g_x + (size_t)n * C + lane * 4);
        float4 o = make_float4(xv.x + acc2[i][0], xv.y + acc2[i][1],
                               xv.z + acc2[i][2], xv.w + acc2[i][3]);
        *(float4*)(out + (size_t)n * C + lane * 4) = o;
    }
}

// ---------------- launch ----------------
extern "C" void kernel_launch(void* const* d_in, const int* in_sizes, int n_in,
                              void* d_out, int out_size)
{
    const float* xf    = (const float*)d_in[0];
    const int*   xi    = (const int*)  d_in[1];
    const float* t     = (const float*)d_in[2];
    const float* z     = (const float*)d_in[3];
    const float* nrm   = (const float*)d_in[4];
    const float* ln1w  = (const float*)d_in[5];
    const float* ln1b  = (const float*)d_in[6];
    const float* ln2w  = (const float*)d_in[7];
    const float* ln2b  = (const float*)d_in[8];
    const float* convw = (const float*)d_in[9];
    const float* t1w   = (const float*)d_in[10];
    const float* t1b   = (const float*)d_in[11];
    const float* t2w   = (const float*)d_in[12];
    const float* t2b   = (const float*)d_in[13];
    const float* z1w1  = (const float*)d_in[14];
    const float* z1b1  = (const float*)d_in[15];
    const float* z1w2  = (const float*)d_in[16];
    const float* z1b2  = (const float*)d_in[17];
    const float* z2w1  = (const float*)d_in[18];
    const float* z2b1  = (const float*)d_in[19];
    const float* z2w2  = (const float*)d_in[20];
    const float* z2b2  = (const float*)d_in[21];
    const float* w1    = (const float*)d_in[22];
    const float* b1    = (const float*)d_in[23];
    const float* w2    = (const float*)d_in[24];
    const float* b2    = (const float*)d_in[25];
    float* out = (float*)d_out;

    fill_grid_kernel<<<(NBATCH * IMG * IMG) / 256, 256>>>();
    scatter_grid_kernel<<<NPTS / 256, 256>>>(xi);

    dim3 mg(NBATCH, 2);
    modvec_kernel<<<mg, 256>>>(t, z, t1w, t1b, t2w, t2b,
                               z1w1, z1b1, z1w2, z1b2,
                               z2w1, z2b1, z2w2, z2b2);

    modulate1_kernel<<<NPTS / 8, 256>>>(xf, ln1w, ln1b);

    conv_kernel<<<NPTS / 64, 256>>>(xf, nrm, xi, convw);

    mlp_kernel<<<NPTS / 32, 256>>>(ln2w, ln2b, w1, b1, w2, b2, out);

    (void)in_sizes; (void)n_in; (void)out_size;
}

// round 3
// speedup vs baseline: 1.3348x; 1.3348x over previous
#include <cuda_runtime.h>
#include <cuda_bf16.h>
#include <math.h>
#include <stdint.h>

// ---------------- problem constants ----------------
#define NBATCH 4
#define IMG    256
#define C      128
#define ACTPTS 32768            // IMG*IMG/2
#define NPTS   (NBATCH*ACTPTS)  // 131072
#define TD     512
#define ZD     256
#define HID    256
#define LN_EPS 1e-5f

// ---------------- scratch (device globals) ----------------
__device__ uint32_t g_h1p[(size_t)NPTS * 128];   // modulated input, packed bf16x2 hi/lo pairs (64 MB)
__device__ float    g_x [(size_t)NPTS * C];      // x = x_features + conv/norm (64 MB)
__device__ int      g_grid[NBATCH * IMG * IMG];
__device__ float    g_tt1[NBATCH * 2 * C];
__device__ float    g_tt2[NBATCH * 2 * C];
__device__ float    g_zz1[NBATCH * C];
__device__ float    g_zz2[NBATCH * C];
// split weights: per k-pair, interleaved {hi-word, lo-word}; each word = bf16x2 (k, k+1)
__device__ uint32_t g_wct[49 * 128 * 128];       // conv: [tap][cout][128 words]
__device__ uint32_t g_w1t[256 * 128];            // mlp w1^T: [n=256][128 words] (K=128)
__device__ uint32_t g_w2t[128 * 256];            // mlp w2^T: [n=128][256 words] (K=256)

__device__ __forceinline__ float gelu_exact(float x) {
    return 0.5f * x * (1.0f + erff(x * 0.70710678118654752440f));
}

__device__ __forceinline__ void split_pair(float a, float b, uint32_t& hi, uint32_t& lo) {
    __nv_bfloat16 ha = __float2bfloat16_rn(a);
    __nv_bfloat16 hb = __float2bfloat16_rn(b);
    __nv_bfloat16 la = __float2bfloat16_rn(a - __bfloat162float(ha));
    __nv_bfloat16 lb = __float2bfloat16_rn(b - __bfloat162float(hb));
    hi = (uint32_t)__bfloat16_as_ushort(ha) | ((uint32_t)__bfloat16_as_ushort(hb) << 16);
    lo = (uint32_t)__bfloat16_as_ushort(la) | ((uint32_t)__bfloat16_as_ushort(lb) << 16);
}

// d += a * b  (m16n8k16 bf16, fp32 accum)
__device__ __forceinline__ void mma_bf16(float* d, const uint32_t* a, const uint32_t* b) {
    asm volatile(
        "mma.sync.aligned.m16n8k16.row.col.f32.bf16.bf16.f32 "
        "{%0,%1,%2,%3},{%4,%5,%6,%7},{%8,%9},{%0,%1,%2,%3};\n"
        : "+f"(d[0]), "+f"(d[1]), "+f"(d[2]), "+f"(d[3])
        : "r"(a[0]), "r"(a[1]), "r"(a[2]), "r"(a[3]), "r"(b[0]), "r"(b[1]));
}

// ---------------- grid build ----------------
__global__ void fill_grid_kernel() {
    int i = blockIdx.x * 256 + threadIdx.x;
    g_grid[i] = -1;
}

__global__ void scatter_grid_kernel(const int* __restrict__ xidx) {
    int n = blockIdx.x * 256 + threadIdx.x;
    int b = xidx[3 * n + 0];
    int y = xidx[3 * n + 1];
    int x = xidx[3 * n + 2];
    g_grid[(b << 16) | (y << 8) | x] = n;
}

// ---------------- weight splitting (hi/lo bf16, transposed) ----------------
#define NCONVP (49 * 128 * 64)
#define NW1P   (256 * 64)
#define NW2P   (128 * 128)
__global__ void split_weights_kernel(const float* __restrict__ convw,
                                     const float* __restrict__ w1,
                                     const float* __restrict__ w2)
{
    int i = blockIdx.x * 256 + threadIdx.x;
    uint32_t hi, lo;
    if (i < NCONVP) {
        int p = i & 63, rest = i >> 6;
        int cout = rest & 127, tap = rest >> 7;
        float a = convw[(tap * 128 + 2 * p + 0) * 128 + cout];
        float b = convw[(tap * 128 + 2 * p + 1) * 128 + cout];
        split_pair(a, b, hi, lo);
        g_wct[(tap * 128 + cout) * 128 + p * 2 + 0] = hi;
        g_wct[(tap * 128 + cout) * 128 + p * 2 + 1] = lo;
    } else if (i < NCONVP + NW1P) {
        int j = i - NCONVP;
        int p = j & 63, n = j >> 6;
        float a = w1[(2 * p + 0) * 256 + n];
        float b = w1[(2 * p + 1) * 256 + n];
        split_pair(a, b, hi, lo);
        g_w1t[n * 128 + p * 2 + 0] = hi;
        g_w1t[n * 128 + p * 2 + 1] = lo;
    } else {
        int j = i - (NCONVP + NW1P);
        int p = j & 127, n = j >> 7;
        float a = w2[(2 * p + 0) * 128 + n];
        float b = w2[(2 * p + 1) * 128 + n];
        split_pair(a, b, hi, lo);
        g_w2t[n * 256 + p * 2 + 0] = hi;
        g_w2t[n * 256 + p * 2 + 1] = lo;
    }
}

// ---------------- per-batch modulation vectors ----------------
__global__ void modvec_kernel(
    const float* __restrict__ t,   const float* __restrict__ z,
    const float* __restrict__ t1w, const float* __restrict__ t1b,
    const float* __restrict__ t2w, const float* __restrict__ t2b,
    const float* __restrict__ z1w1, const float* __restrict__ z1b1,
    const float* __restrict__ z1w2, const float* __restrict__ z1b2,
    const float* __restrict__ z2w1, const float* __restrict__ z2b1,
    const float* __restrict__ z2w2, const float* __restrict__ z2b2)
{
    const int b   = blockIdx.x;
    const int tid = threadIdx.x;

    if (blockIdx.y == 0) {
        __shared__ float gt[TD];
        gt[tid]       = gelu_exact(t[b * TD + tid]);
        gt[tid + 256] = gelu_exact(t[b * TD + tid + 256]);
        __syncthreads();
        float a1 = t1b[tid], a2 = t2b[tid];
        #pragma unroll 8
        for (int k = 0; k < TD; k++) {
            float g = gt[k];
            a1 += g * t1w[k * 256 + tid];
            a2 += g * t2w[k * 256 + tid];
        }
        g_tt1[b * 256 + tid] = a1;
        g_tt2[b * 256 + tid] = a2;
    } else {
        __shared__ float gz[ZD];
        __shared__ float hz[2 * C];
        gz[tid] = z[b * ZD + tid];
        __syncthreads();
        {
            int j = tid & 127;
            const float* w  = (tid < 128) ? z1w1 : z2w1;
            const float* bb = (tid < 128) ? z1b1 : z2b1;
            float a = bb[j];
            #pragma unroll 8
            for (int k = 0; k < ZD; k++) a += gz[k] * w[k * C + j];
            hz[tid] = gelu_exact(a);
        }
        __syncthreads();
        {
            int j = tid & 127;
            const float* w  = (tid < 128) ? z1w2 : z2w2;
            const float* bb = (tid < 128) ? z1b2 : z2b2;
            const float* h  = (tid < 128) ? hz : (hz + C);
            float a = bb[j];
            #pragma unroll 8
            for (int k = 0; k < C; k++) a += h[k] * w[k * C + j];
            if (tid < 128) g_zz1[b * C + j] = a;
            else           g_zz2[b * C + j] = a;
        }
    }
}

// ---------------- stage-1 modulate: LN + t/z modulation -> g_h1p (split bf16) --------
__global__ void modulate1_kernel(const float* __restrict__ xf,
                                 const float* __restrict__ lnw,
                                 const float* __restrict__ lnb)
{
    const int warp = threadIdx.x >> 5;
    const int lane = threadIdx.x & 31;
    const int n = blockIdx.x * 8 + warp;
    const int b = n >> 15;

    float4 v = *(const float4*)(xf + (size_t)n * C + lane * 4);
    float s  = v.x + v.y + v.z + v.w;
    float sq = v.x * v.x + v.y * v.y + v.z * v.z + v.w * v.w;
    #pragma unroll
    for (int o = 16; o; o >>= 1) {
        s  += __shfl_xor_sync(0xffffffffu, s,  o);
        sq += __shfl_xor_sync(0xffffffffu, sq, o);
    }
    float mu = s * (1.0f / C);
    float rs = rsqrtf(sq * (1.0f / C) - mu * mu + LN_EPS);

    float vv[4] = {v.x, v.y, v.z, v.w};
    float o4[4];
    #pragma unroll
    for (int u = 0; u < 4; u++) {
        int c = lane * 4 + u;
        float f = (vv[u] - mu) * rs * lnw[c] + lnb[c];
        f = f * (1.0f + g_tt1[b * 256 + c]) + g_tt1[b * 256 + 128 + c];
        o4[u] = f * (1.0f + g_zz1[b * 128 + c]);
    }
    uint4 pk;
    split_pair(o4[0], o4[1], pk.x, pk.y);
    split_pair(o4[2], o4[3], pk.z, pk.w);
    *(uint4*)(g_h1p + (size_t)n * 128 + lane * 4) = pk;
}

// ---------------- sparse 7x7 conv via split-bf16 tensor-core GEMM ----------------
// Block: 128 points x 128 couts, 256 threads (8 warps: wm 0..3 x wn 0..1).
// Warp tile: m32 x n64.  smem: As/Bs stride 136 words (68 pairs) -> conflict-free LDS.64.
#define ASTRIDE 136
__global__ __launch_bounds__(256) void conv_kernel(
    const float* __restrict__ xf, const float* __restrict__ nrm,
    const int* __restrict__ xidx)
{
    extern __shared__ uint32_t smem[];
    uint32_t* As = smem;                  // 128 * 136
    uint32_t* Bs = smem + 128 * ASTRIDE;  // 128 * 136
    __shared__ int   nb[128];
    __shared__ int   sb[128], sy[128], sx[128];
    __shared__ float sInv[128];

    const int tid  = threadIdx.x;
    const int base = blockIdx.x * 128;
    const int warp = tid >> 5, lane = tid & 31;
    const int wm = warp >> 1, wn = warp & 1;
    const int lq = lane >> 2, lr = lane & 3;

    if (tid < 128) {
        int n = base + tid;
        sb[tid]   = xidx[3 * n + 0] << 16;
        sy[tid]   = xidx[3 * n + 1];
        sx[tid]   = xidx[3 * n + 2];
        sInv[tid] = 1.0f / nrm[n];
    }

    float acc[2][8][4];
    #pragma unroll
    for (int mt = 0; mt < 2; mt++)
        #pragma unroll
        for (int nj = 0; nj < 8; nj++)
            #pragma unroll
            for (int q = 0; q < 4; q++) acc[mt][nj][q] = 0.0f;

    const int r  = tid >> 1;     // staging row 0..127
    const int hh = tid & 1;      // k-half
    uint4* aDst = (uint4*)(As + r * ASTRIDE + hh * 64);
    uint4* bDst = (uint4*)(Bs + r * ASTRIDE + hh * 64);

    for (int tap = 0; tap < 49; tap++) {
        __syncthreads();    // previous MMA done; safe to overwrite nb/As/Bs
        if (tid < 128) {
            int ky = tap / 7 - 3, kx = tap % 7 - 3;
            int ny = sy[tid] + ky, nx = sx[tid] + kx;
            int v = -1;
            if ((unsigned)ny < 256u && (unsigned)nx < 256u)
                v = g_grid[sb[tid] | (ny << 8) | nx];
            nb[tid] = v;
        }
        __syncthreads();

        // stage A (gather, already-split bf16 pairs) and B (pre-split weights)
        {
            int src = nb[r];
            if (src >= 0) {
                const uint4* sp = (const uint4*)(g_h1p + (size_t)src * 128 + hh * 64);
                #pragma unroll
                for (int j = 0; j < 16; j++) aDst[j] = sp[j];
            } else {
                uint4 zz = make_uint4(0, 0, 0, 0);
                #pragma unroll
                for (int j = 0; j < 16; j++) aDst[j] = zz;
            }
            const uint4* wp = (const uint4*)(g_wct + tap * 16384 + r * 128 + hh * 64);
            #pragma unroll
            for (int j = 0; j < 16; j++) bDst[j] = wp[j];
        }
        __syncthreads();

        // MMA: 8 k-steps of k16, 3 passes (hi*hi, hi*lo, lo*hi)
        #pragma unroll
        for (int ks = 0; ks < 8; ks++) {
            uint32_t ah[2][4], al[2][4];
            #pragma unroll
            for (int mt = 0; mt < 2; mt++) {
                const uint32_t* ap = As + (wm * 32 + mt * 16 + lq) * ASTRIDE + (ks * 8 + lr) * 2;
                uint2 v0 = *(const uint2*)(ap);
                uint2 v1 = *(const uint2*)(ap + 8 * ASTRIDE);
                uint2 v2 = *(const uint2*)(ap + 8);
                uint2 v3 = *(const uint2*)(ap + 8 * ASTRIDE + 8);
                ah[mt][0] = v0.x; al[mt][0] = v0.y;
                ah[mt][1] = v1.x; al[mt][1] = v1.y;
                ah[mt][2] = v2.x; al[mt][2] = v2.y;
                ah[mt][3] = v3.x; al[mt][3] = v3.y;
            }
            #pragma unroll
            for (int nj = 0; nj < 8; nj++) {
                const uint32_t* bp = Bs + (wn * 64 + nj * 8 + lq) * ASTRIDE + (ks * 8 + lr) * 2;
                uint2 u0 = *(const uint2*)(bp);
                uint2 u1 = *(const uint2*)(bp + 8);
                uint32_t bh[2] = {u0.x, u1.x};
                uint32_t bl[2] = {u0.y, u1.y};
                #pragma unroll
                for (int mt = 0; mt < 2; mt++) {
                    mma_bf16(acc[mt][nj], ah[mt], bh);
                    mma_bf16(acc[mt][nj], ah[mt], bl);
                    mma_bf16(acc[mt][nj], al[mt], bh);
                }
            }
        }
    }

    // epilogue: x = x_features + conv/norm
    #pragma unroll
    for (int mt = 0; mt < 2; mt++) {
        int m = wm * 32 + mt * 16 + lq;
        #pragma unroll
        for (int nj = 0; nj < 8; nj++) {
            int n0 = wn * 64 + nj * 8 + lr * 2;
            {
                int gm = base + m;
                float inv = sInv[m];
                float2 x0 = *(const float2*)(xf + (size_t)gm * C + n0);
                float2 o;
                o.x = x0.x + acc[mt][nj][0] * inv;
                o.y = x0.y + acc[mt][nj][1] * inv;
                *(float2*)(g_x + (size_t)gm * C + n0) = o;
            }
            {
                int gm = base + m + 8;
                float inv = sInv[m + 8];
                float2 x1 = *(const float2*)(xf + (size_t)gm * C + n0);
                float2 o;
                o.x = x1.x + acc[mt][nj][2] * inv;
                o.y = x1.y + acc[mt][nj][3] * inv;
                *(float2*)(g_x + (size_t)gm * C + n0) = o;
            }
        }
    }
}

// ---------------- stage-2: LN2 + modulation + MLP (tensor cores) + residual ----------
// Block: 64 rows, 256 threads. Warp w covers distinct n-range; all m-tiles per warp.
#define HSTRIDE 264
__global__ __launch_bounds__(256) void mlp_kernel(
    const float* __restrict__ lnw, const float* __restrict__ lnb,
    const float* __restrict__ b1,  const float* __restrict__ b2,
    float* __restrict__ out)
{
    extern __shared__ uint32_t smem[];
    uint32_t* As = smem;                  // 64 * 136
    uint32_t* Hs = smem + 64 * ASTRIDE;   // 64 * 264
    const int tid  = threadIdx.x;
    const int warp = tid >> 5, lane = tid & 31;
    const int lq = lane >> 2, lr = lane & 3;
    const int base = blockIdx.x * 64;

    // phase 1: LN + modulation, split to bf16 pairs in As
    #pragma unroll
    for (int rr = 0; rr < 8; rr++) {
        int rl = warp * 8 + rr;
        int n  = base + rl;
        int b  = n >> 15;
        float4 v = *(const float4*)(g_x + (size_t)n * C + lane * 4);
        float s  = v.x + v.y + v.z + v.w;
        float sq = v.x * v.x + v.y * v.y + v.z * v.z + v.w * v.w;
        #pragma unroll
        for (int o = 16; o; o >>= 1) {
            s  += __shfl_xor_sync(0xffffffffu, s,  o);
            sq += __shfl_xor_sync(0xffffffffu, sq, o);
        }
        float mu = s * (1.0f / C);
        float rs = rsqrtf(sq * (1.0f / C) - mu * mu + LN_EPS);
        float vv[4] = {v.x, v.y, v.z, v.w};
        float o4[4];
        #pragma unroll
        for (int u = 0; u < 4; u++) {
            int c = lane * 4 + u;
            float f = (vv[u] - mu) * rs * lnw[c] + lnb[c];
            f = f * (1.0f + g_tt2[b * 256 + c]) + g_tt2[b * 256 + 128 + c];
            o4[u] = f * (1.0f + g_zz2[b * 128 + c]);
        }
        uint4 pk;
        split_pair(o4[0], o4[1], pk.x, pk.y);
        split_pair(o4[2], o4[3], pk.z, pk.w);
        *(uint4*)(As + rl * ASTRIDE + lane * 4) = pk;
    }
    __syncthreads();

    // GEMM1: H = gelu(A @ w1 + b1); warp covers n in [warp*32, warp*32+32)
    float acc1[4][4][4];
    #pragma unroll
    for (int mt = 0; mt < 4; mt++)
        #pragma unroll
        for (int nj = 0; nj < 4; nj++)
            #pragma unroll
            for (int q = 0; q < 4; q++) acc1[mt][nj][q] = 0.0f;

    #pragma unroll
    for (int ks = 0; ks < 8; ks++) {
        uint32_t ah[4][4], al[4][4];
        #pragma unroll
        for (int mt = 0; mt < 4; mt++) {
            const uint32_t* ap = As + (mt * 16 + lq) * ASTRIDE + (ks * 8 + lr) * 2;
            uint2 v0 = *(const uint2*)(ap);
            uint2 v1 = *(const uint2*)(ap + 8 * ASTRIDE);
            uint2 v2 = *(const uint2*)(ap + 8);
            uint2 v3 = *(const uint2*)(ap + 8 * ASTRIDE + 8);
            ah[mt][0] = v0.x; al[mt][0] = v0.y;
            ah[mt][1] = v1.x; al[mt][1] = v1.y;
            ah[mt][2] = v2.x; al[mt][2] = v2.y;
            ah[mt][3] = v3.x; al[mt][3] = v3.y;
        }
        #pragma unroll
        for (int nj = 0; nj < 4; nj++) {
            const uint32_t* bp = g_w1t + (warp * 32 + nj * 8 + lq) * 128 + (ks * 8 + lr) * 2;
            uint2 u0 = *(const uint2*)(bp);
            uint2 u1 = *(const uint2*)(bp + 8);
            uint32_t bh[2] = {u0.x, u1.x};
            uint32_t bl[2] = {u0.y, u1.y};
            #pragma unroll
            for (int mt = 0; mt < 4; mt++) {
                mma_bf16(acc1[mt][nj], ah[mt], bh);
                mma_bf16(acc1[mt][nj], ah[mt], bl);
                mma_bf16(acc1[mt][nj], al[mt], bh);
            }
        }
    }
    // bias + gelu, split into Hs
    #pragma unroll
    for (int nj = 0; nj < 4; nj++) {
        int n0 = warp * 32 + nj * 8 + lr * 2;
        float2 bb = *(const float2*)(b1 + n0);
        int pair = n0 >> 1;
        #pragma unroll
        for (int mt = 0; mt < 4; mt++) {
            int m0 = mt * 16 + lq;
            uint2 w0, w1v;
            split_pair(gelu_exact(acc1[mt][nj][0] + bb.x),
                       gelu_exact(acc1[mt][nj][1] + bb.y), w0.x, w0.y);
            split_pair(gelu_exact(acc1[mt][nj][2] + bb.x),
                       gelu_exact(acc1[mt][nj][3] + bb.y), w1v.x, w1v.y);
            *(uint2*)(Hs + m0 * HSTRIDE + pair * 2) = w0;
            *(uint2*)(Hs + (m0 + 8) * HSTRIDE + pair * 2) = w1v;
        }
    }
    __syncthreads();

    // GEMM2: out = x + H @ w2 + b2; warp covers n in [warp*16, warp*16+16); K=256
    float acc2[4][2][4];
    #pragma unroll
    for (int mt = 0; mt < 4; mt++)
        #pragma unroll
        for (int nj = 0; nj < 2; nj++)
            #pragma unroll
            for (int q = 0; q < 4; q++) acc2[mt][nj][q] = 0.0f;

    #pragma unroll
    for (int ks = 0; ks < 16; ks++) {
        uint32_t ah[4][4], al[4][4];
        #pragma unroll
        for (int mt = 0; mt < 4; mt++) {
            const uint32_t* ap = Hs + (mt * 16 + lq) * HSTRIDE + (ks * 8 + lr) * 2;
            uint2 v0 = *(const uint2*)(ap);
            uint2 v1 = *(const uint2*)(ap + 8 * HSTRIDE);
            uint2 v2 = *(const uint2*)(ap + 8);
            uint2 v3 = *(const uint2*)(ap + 8 * HSTRIDE + 8);
            ah[mt][0] = v0.x; al[mt][0] = v0.y;
            ah[mt][1] = v1.x; al[mt][1] = v1.y;
            ah[mt][2] = v2.x; al[mt][2] = v2.y;
            ah[mt][3] = v3.x; al[mt][3] = v3.y;
        }
        #pragma unroll
        for (int nj = 0; nj < 2; nj++) {
            const uint32_t* bp = g_w2t + (warp * 16 + nj * 8 + lq) * 256 + (ks * 8 + lr) * 2;
            uint2 u0 = *(const uint2*)(bp);
            uint2 u1 = *(const uint2*)(bp + 8);
            uint32_t bh[2] = {u0.x, u1.x};
            uint32_t bl[2] = {u0.y, u1.y};
            #pragma unroll
            for (int mt = 0; mt < 4; mt++) {
                mma_bf16(acc2[mt][nj], ah[mt], bh);
                mma_bf16(acc2[mt][nj], ah[mt], bl);
                mma_bf16(acc2[mt][nj], al[mt], bh);
            }
        }
    }
    // epilogue: bias + residual
    #pragma unroll
    for (int nj = 0; nj < 2; nj++) {
        int n0 = warp * 16 + nj * 8 + lr * 2;
        float2 bb = *(const float2*)(b2 + n0);
        #pragma unroll
        for (int mt = 0; mt < 4; mt++) {
            int m0 = mt * 16 + lq;
            {
                int gm = base + m0;
                float2 x = *(const float2*)(g_x + (size_t)gm * C + n0);
                float2 o;
                o.x = x.x + acc2[mt][nj][0] + bb.x;
                o.y = x.y + acc2[mt][nj][1] + bb.y;
                *(float2*)(out + (size_t)gm * C + n0) = o;
            }
            {
                int gm = base + m0 + 8;
                float2 x = *(const float2*)(g_x + (size_t)gm * C + n0);
                float2 o;
                o.x = x.x + acc2[mt][nj][2] + bb.x;
                o.y = x.y + acc2[mt][nj][3] + bb.y;
                *(float2*)(out + (size_t)gm * C + n0) = o;
            }
        }
    }
}

// ---------------- launch ----------------
extern "C" void kernel_launch(void* const* d_in, const int* in_sizes, int n_in,
                              void* d_out, int out_size)
{
    const float* xf    = (const float*)d_in[0];
    const int*   xi    = (const int*)  d_in[1];
    const float* t     = (const float*)d_in[2];
    const float* z     = (const float*)d_in[3];
    const float* nrm   = (const float*)d_in[4];
    const float* ln1w  = (const float*)d_in[5];
    const float* ln1b  = (const float*)d_in[6];
    const float* ln2w  = (const float*)d_in[7];
    const float* ln2b  = (const float*)d_in[8];
    const float* convw = (const float*)d_in[9];
    const float* t1w   = (const float*)d_in[10];
    const float* t1b   = (const float*)d_in[11];
    const float* t2w   = (const float*)d_in[12];
    const float* t2b   = (const float*)d_in[13];
    const float* z1w1  = (const float*)d_in[14];
    const float* z1b1  = (const float*)d_in[15];
    const float* z1w2  = (const float*)d_in[16];
    const float* z1b2  = (const float*)d_in[17];
    const float* z2w1  = (const float*)d_in[18];
    const float* z2b1  = (const float*)d_in[19];
    const float* z2w2  = (const float*)d_in[20];
    const float* z2b2  = (const float*)d_in[21];
    const float* w1    = (const float*)d_in[22];
    const float* b1    = (const float*)d_in[23];
    const float* w2    = (const float*)d_in[24];
    const float* b2    = (const float*)d_in[25];
    float* out = (float*)d_out;

    const int CONV_SMEM = 2 * 128 * ASTRIDE * 4;               // 139264
    const int MLP_SMEM  = (64 * ASTRIDE + 64 * HSTRIDE) * 4;   // 102400
    cudaFuncSetAttribute(conv_kernel, cudaFuncAttributeMaxDynamicSharedMemorySize, CONV_SMEM);
    cudaFuncSetAttribute(mlp_kernel,  cudaFuncAttributeMaxDynamicSharedMemorySize, MLP_SMEM);

    fill_grid_kernel<<<(NBATCH * IMG * IMG) / 256, 256>>>();
    scatter_grid_kernel<<<NPTS / 256, 256>>>(xi);

    dim3 mg(NBATCH, 2);
    modvec_kernel<<<mg, 256>>>(t, z, t1w, t1b, t2w, t2b,
                               z1w1, z1b1, z1w2, z1b2,
                               z2w1, z2b1, z2w2, z2b2);

    split_weights_kernel<<<(NCONVP + NW1P + NW2P) / 256, 256>>>(convw, w1, w2);

    modulate1_kernel<<<NPTS / 8, 256>>>(xf, ln1w, ln1b);

    conv_kernel<<<NPTS / 128, 256, CONV_SMEM>>>(xf, nrm, xi);

    mlp_kernel<<<NPTS / 64, 256, MLP_SMEM>>>(ln2w, ln2b, b1, b2, out);

    (void)in_sizes; (void)n_in; (void)out_size;
}

// round 4
// speedup vs baseline: 1.3353x; 1.0004x over previous
#include <cuda_runtime.h>
#include <cuda_bf16.h>
#include <math.h>
#include <stdint.h>

// ---------------- problem constants ----------------
#define NBATCH 4
#define IMG    256
#define C      128
#define ACTPTS 32768            // IMG*IMG/2
#define NPTS   (NBATCH*ACTPTS)  // 131072
#define TD     512
#define ZD     256
#define HID    256
#define LN_EPS 1e-5f

// ---------------- scratch (device globals) ----------------
__device__ uint32_t g_h1p[(size_t)NPTS * 128];   // modulated input, packed bf16x2 hi/lo pairs (64 MB)
__device__ float    g_x [(size_t)NPTS * C];      // x = x_features + conv/norm (64 MB)
__device__ int      g_grid[NBATCH * IMG * IMG];
__device__ float    g_tt1[NBATCH * 2 * C];
__device__ float    g_tt2[NBATCH * 2 * C];
__device__ float    g_zz1[NBATCH * C];
__device__ float    g_zz2[NBATCH * C];
// split weights: per k-pair, interleaved {hi-word, lo-word}; each word = bf16x2 (k, k+1)
__device__ uint32_t g_wct[49 * 128 * 128];       // conv: [tap][cout][128 words]
__device__ uint32_t g_w1t[256 * 128];            // mlp w1^T: [n=256][128 words] (K=128)
__device__ uint32_t g_w2t[128 * 256];            // mlp w2^T: [n=128][256 words] (K=256)

__device__ __forceinline__ float gelu_exact(float x) {
    return 0.5f * x * (1.0f + erff(x * 0.70710678118654752440f));
}

__device__ __forceinline__ void split_pair(float a, float b, uint32_t& hi, uint32_t& lo) {
    __nv_bfloat16 ha = __float2bfloat16_rn(a);
    __nv_bfloat16 hb = __float2bfloat16_rn(b);
    __nv_bfloat16 la = __float2bfloat16_rn(a - __bfloat162float(ha));
    __nv_bfloat16 lb = __float2bfloat16_rn(b - __bfloat162float(hb));
    hi = (uint32_t)__bfloat16_as_ushort(ha) | ((uint32_t)__bfloat16_as_ushort(hb) << 16);
    lo = (uint32_t)__bfloat16_as_ushort(la) | ((uint32_t)__bfloat16_as_ushort(lb) << 16);
}

// d += a * b  (m16n8k16 bf16, fp32 accum)
__device__ __forceinline__ void mma_bf16(float* d, const uint32_t* a, const uint32_t* b) {
    asm volatile(
        "mma.sync.aligned.m16n8k16.row.col.f32.bf16.bf16.f32 "
        "{%0,%1,%2,%3},{%4,%5,%6,%7},{%8,%9},{%0,%1,%2,%3};\n"
        : "+f"(d[0]), "+f"(d[1]), "+f"(d[2]), "+f"(d[3])
        : "r"(a[0]), "r"(a[1]), "r"(a[2]), "r"(a[3]), "r"(b[0]), "r"(b[1]));
}

// ---------------- grid build ----------------
__global__ void fill_grid_kernel() {
    int i = blockIdx.x * 256 + threadIdx.x;
    g_grid[i] = -1;
}

__global__ void scatter_grid_kernel(const int* __restrict__ xidx) {
    int n = blockIdx.x * 256 + threadIdx.x;
    int b = xidx[3 * n + 0];
    int y = xidx[3 * n + 1];
    int x = xidx[3 * n + 2];
    g_grid[(b << 16) | (y << 8) | x] = n;
}

// ---------------- weight splitting (hi/lo bf16, transposed) ----------------
#define NCONVP (49 * 128 * 64)
#define NW1P   (256 * 64)
#define NW2P   (128 * 128)
__global__ void split_weights_kernel(const float* __restrict__ convw,
                                     const float* __restrict__ w1,
                                     const float* __restrict__ w2)
{
    int i = blockIdx.x * 256 + threadIdx.x;
    uint32_t hi, lo;
    if (i < NCONVP) {
        int p = i & 63, rest = i >> 6;
        int cout = rest & 127, tap = rest >> 7;
        float a = convw[(tap * 128 + 2 * p + 0) * 128 + cout];
        float b = convw[(tap * 128 + 2 * p + 1) * 128 + cout];
        split_pair(a, b, hi, lo);
        g_wct[(tap * 128 + cout) * 128 + p * 2 + 0] = hi;
        g_wct[(tap * 128 + cout) * 128 + p * 2 + 1] = lo;
    } else if (i < NCONVP + NW1P) {
        int j = i - NCONVP;
        int p = j & 63, n = j >> 6;
        float a = w1[(2 * p + 0) * 256 + n];
        float b = w1[(2 * p + 1) * 256 + n];
        split_pair(a, b, hi, lo);
        g_w1t[n * 128 + p * 2 + 0] = hi;
        g_w1t[n * 128 + p * 2 + 1] = lo;
    } else {
        int j = i - (NCONVP + NW1P);
        int p = j & 127, n = j >> 7;
        float a = w2[(2 * p + 0) * 128 + n];
        float b = w2[(2 * p + 1) * 128 + n];
        split_pair(a, b, hi, lo);
        g_w2t[n * 256 + p * 2 + 0] = hi;
        g_w2t[n * 256 + p * 2 + 1] = lo;
    }
}

// ---------------- per-batch modulation vectors ----------------
__global__ void modvec_kernel(
    const float* __restrict__ t,   const float* __restrict__ z,
    const float* __restrict__ t1w, const float* __restrict__ t1b,
    const float* __restrict__ t2w, const float* __restrict__ t2b,
    const float* __restrict__ z1w1, const float* __restrict__ z1b1,
    const float* __restrict__ z1w2, const float* __restrict__ z1b2,
    const float* __restrict__ z2w1, const float* __restrict__ z2b1,
    const float* __restrict__ z2w2, const float* __restrict__ z2b2)
{
    const int b   = blockIdx.x;
    const int tid = threadIdx.x;

    if (blockIdx.y == 0) {
        __shared__ float gt[TD];
        gt[tid]       = gelu_exact(t[b * TD + tid]);
        gt[tid + 256] = gelu_exact(t[b * TD + tid + 256]);
        __syncthreads();
        float a1 = t1b[tid], a2 = t2b[tid];
        #pragma unroll 8
        for (int k = 0; k < TD; k++) {
            float g = gt[k];
            a1 += g * t1w[k * 256 + tid];
            a2 += g * t2w[k * 256 + tid];
        }
        g_tt1[b * 256 + tid] = a1;
        g_tt2[b * 256 + tid] = a2;
    } else {
        __shared__ float gz[ZD];
        __shared__ float hz[2 * C];
        gz[tid] = z[b * ZD + tid];
        __syncthreads();
        {
            int j = tid & 127;
            const float* w  = (tid < 128) ? z1w1 : z2w1;
            const float* bb = (tid < 128) ? z1b1 : z2b1;
            float a = bb[j];
            #pragma unroll 8
            for (int k = 0; k < ZD; k++) a += gz[k] * w[k * C + j];
            hz[tid] = gelu_exact(a);
        }
        __syncthreads();
        {
            int j = tid & 127;
            const float* w  = (tid < 128) ? z1w2 : z2w2;
            const float* bb = (tid < 128) ? z1b2 : z2b2;
            const float* h  = (tid < 128) ? hz : (hz + C);
            float a = bb[j];
            #pragma unroll 8
            for (int k = 0; k < C; k++) a += h[k] * w[k * C + j];
            if (tid < 128) g_zz1[b * C + j] = a;
            else           g_zz2[b * C + j] = a;
        }
    }
}

// ---------------- stage-1 modulate: LN + t/z modulation -> g_h1p (split bf16) --------
__global__ void modulate1_kernel(const float* __restrict__ xf,
                                 const float* __restrict__ lnw,
                                 const float* __restrict__ lnb)
{
    const int warp = threadIdx.x >> 5;
    const int lane = threadIdx.x & 31;
    const int n = blockIdx.x * 8 + warp;
    const int b = n >> 15;

    float4 v = *(const float4*)(xf + (size_t)n * C + lane * 4);
    float s  = v.x + v.y + v.z + v.w;
    float sq = v.x * v.x + v.y * v.y + v.z * v.z + v.w * v.w;
    #pragma unroll
    for (int o = 16; o; o >>= 1) {
        s  += __shfl_xor_sync(0xffffffffu, s,  o);
        sq += __shfl_xor_sync(0xffffffffu, sq, o);
    }
    float mu = s * (1.0f / C);
    float rs = rsqrtf(sq * (1.0f / C) - mu * mu + LN_EPS);

    float vv[4] = {v.x, v.y, v.z, v.w};
    float o4[4];
    #pragma unroll
    for (int u = 0; u < 4; u++) {
        int c = lane * 4 + u;
        float f = (vv[u] - mu) * rs * lnw[c] + lnb[c];
        f = f * (1.0f + g_tt1[b * 256 + c]) + g_tt1[b * 256 + 128 + c];
        o4[u] = f * (1.0f + g_zz1[b * 128 + c]);
    }
    uint4 pk;
    split_pair(o4[0], o4[1], pk.x, pk.y);
    split_pair(o4[2], o4[3], pk.z, pk.w);
    *(uint4*)(g_h1p + (size_t)n * 128 + lane * 4) = pk;
}

// ---------------- sparse 7x7 conv via split-bf16 tensor-core GEMM ----------------
// Block: 128 points x 128 couts, 256 threads (8 warps: wm 0..3 x wn 0..1).
// Warp tile: m32 x n64.  smem: As/Bs stride 136 words (68 pairs) -> conflict-free LDS.64.
#define ASTRIDE 136
__global__ __launch_bounds__(256) void conv_kernel(
    const float* __restrict__ xf, const float* __restrict__ nrm,
    const int* __restrict__ xidx)
{
    extern __shared__ uint32_t smem[];
    uint32_t* As = smem;                  // 128 * 136
    uint32_t* Bs = smem + 128 * ASTRIDE;  // 128 * 136
    __shared__ int   nb[128];
    __shared__ int   sb[128], sy[128], sx[128];
    __shared__ float sInv[128];

    const int tid  = threadIdx.x;
    const int base = blockIdx.x * 128;
    const int warp = tid >> 5, lane = tid & 31;
    const int wm = warp >> 1, wn = warp & 1;
    const int lq = lane >> 2, lr = lane & 3;

    if (tid < 128) {
        int n = base + tid;
        sb[tid]   = xidx[3 * n + 0] << 16;
        sy[tid]   = xidx[3 * n + 1];
        sx[tid]   = xidx[3 * n + 2];
        sInv[tid] = 1.0f / nrm[n];
    }

    float acc[2][8][4];
    #pragma unroll
    for (int mt = 0; mt < 2; mt++)
        #pragma unroll
        for (int nj = 0; nj < 8; nj++)
            #pragma unroll
            for (int q = 0; q < 4; q++) acc[mt][nj][q] = 0.0f;

    const int r  = tid >> 1;     // staging row 0..127
    const int hh = tid & 1;      // k-half
    uint4* aDst = (uint4*)(As + r * ASTRIDE + hh * 64);
    uint4* bDst = (uint4*)(Bs + r * ASTRIDE + hh * 64);

    for (int tap = 0; tap < 49; tap++) {
        __syncthreads();    // previous MMA done; safe to overwrite nb/As/Bs
        if (tid < 128) {
            int ky = tap / 7 - 3, kx = tap % 7 - 3;
            int ny = sy[tid] + ky, nx = sx[tid] + kx;
            int v = -1;
            if ((unsigned)ny < 256u && (unsigned)nx < 256u)
                v = g_grid[sb[tid] | (ny << 8) | nx];
            nb[tid] = v;
        }
        __syncthreads();

        // stage A (gather, already-split bf16 pairs) and B (pre-split weights)
        {
            int src = nb[r];
            if (src >= 0) {
                const uint4* sp = (const uint4*)(g_h1p + (size_t)src * 128 + hh * 64);
                #pragma unroll
                for (int j = 0; j < 16; j++) aDst[j] = sp[j];
            } else {
                uint4 zz = make_uint4(0, 0, 0, 0);
                #pragma unroll
                for (int j = 0; j < 16; j++) aDst[j] = zz;
            }
            const uint4* wp = (const uint4*)(g_wct + tap * 16384 + r * 128 + hh * 64);
            #pragma unroll
            for (int j = 0; j < 16; j++) bDst[j] = wp[j];
        }
        __syncthreads();

        // MMA: 8 k-steps of k16, 3 passes (hi*hi, hi*lo, lo*hi)
        #pragma unroll
        for (int ks = 0; ks < 8; ks++) {
            uint32_t ah[2][4], al[2][4];
            #pragma unroll
            for (int mt = 0; mt < 2; mt++) {
                const uint32_t* ap = As + (wm * 32 + mt * 16 + lq) * ASTRIDE + (ks * 8 + lr) * 2;
                uint2 v0 = *(const uint2*)(ap);
                uint2 v1 = *(const uint2*)(ap + 8 * ASTRIDE);
                uint2 v2 = *(const uint2*)(ap + 8);
                uint2 v3 = *(const uint2*)(ap + 8 * ASTRIDE + 8);
                ah[mt][0] = v0.x; al[mt][0] = v0.y;
                ah[mt][1] = v1.x; al[mt][1] = v1.y;
                ah[mt][2] = v2.x; al[mt][2] = v2.y;
                ah[mt][3] = v3.x; al[mt][3] = v3.y;
            }
            #pragma unroll
            for (int nj = 0; nj < 8; nj++) {
                const uint32_t* bp = Bs + (wn * 64 + nj * 8 + lq) * ASTRIDE + (ks * 8 + lr) * 2;
                uint2 u0 = *(const uint2*)(bp);
                uint2 u1 = *(const uint2*)(bp + 8);
                uint32_t bh[2] = {u0.x, u1.x};
                uint32_t bl[2] = {u0.y, u1.y};
                #pragma unroll
                for (int mt = 0; mt < 2; mt++) {
                    mma_bf16(acc[mt][nj], ah[mt], bh);
                    mma_bf16(acc[mt][nj], ah[mt], bl);
                    mma_bf16(acc[mt][nj], al[mt], bh);
                }
            }
        }
    }

    // epilogue: x = x_features + conv/norm
    #pragma unroll
    for (int mt = 0; mt < 2; mt++) {
        int m = wm * 32 + mt * 16 + lq;
        #pragma unroll
        for (int nj = 0; nj < 8; nj++) {
            int n0 = wn * 64 + nj * 8 + lr * 2;
            {
                int gm = base + m;
                float inv = sInv[m];
                float2 x0 = *(const float2*)(xf + (size_t)gm * C + n0);
                float2 o;
                o.x = x0.x + acc[mt][nj][0] * inv;
                o.y = x0.y + acc[mt][nj][1] * inv;
                *(float2*)(g_x + (size_t)gm * C + n0) = o;
            }
            {
                int gm = base + m + 8;
                float inv = sInv[m + 8];
                float2 x1 = *(const float2*)(xf + (size_t)gm * C + n0);
                float2 o;
                o.x = x1.x + acc[mt][nj][2] * inv;
                o.y = x1.y + acc[mt][nj][3] * inv;
                *(float2*)(g_x + (size_t)gm * C + n0) = o;
            }
        }
    }
}

// ---------------- stage-2: LN2 + modulation + MLP (tensor cores) + residual ----------
// Block: 64 rows, 256 threads. Warp w covers distinct n-range; all m-tiles per warp.
#define HSTRIDE 264
__global__ __launch_bounds__(256) void mlp_kernel(
    const float* __restrict__ lnw, const float* __restrict__ lnb,
    const float* __restrict__ b1,  const float* __restrict__ b2,
    float* __restrict__ out)
{
    extern __shared__ uint32_t smem[];
    uint32_t* As = smem;                  // 64 * 136
    uint32_t* Hs = smem + 64 * ASTRIDE;   // 64 * 264
    const int tid  = threadIdx.x;
    const int warp = tid >> 5, lane = tid & 31;
    const int lq = lane >> 2, lr = lane & 3;
    const int base = blockIdx.x * 64;

    // phase 1: LN + modulation, split to bf16 pairs in As
    #pragma unroll
    for (int rr = 0; rr < 8; rr++) {
        int rl = warp * 8 + rr;
        int n  = base + rl;
        int b  = n >> 15;
        float4 v = *(const float4*)(g_x + (size_t)n * C + lane * 4);
        float s  = v.x + v.y + v.z + v.w;
        float sq = v.x * v.x + v.y * v.y + v.z * v.z + v.w * v.w;
        #pragma unroll
        for (int o = 16; o; o >>= 1) {
            s  += __shfl_xor_sync(0xffffffffu, s,  o);
            sq += __shfl_xor_sync(0xffffffffu, sq, o);
        }
        float mu = s * (1.0f / C);
        float rs = rsqrtf(sq * (1.0f / C) - mu * mu + LN_EPS);
        float vv[4] = {v.x, v.y, v.z, v.w};
        float o4[4];
        #pragma unroll
        for (int u = 0; u < 4; u++) {
            int c = lane * 4 + u;
            float f = (vv[u] - mu) * rs * lnw[c] + lnb[c];
            f = f * (1.0f + g_tt2[b * 256 + c]) + g_tt2[b * 256 + 128 + c];
            o4[u] = f * (1.0f + g_zz2[b * 128 + c]);
        }
        uint4 pk;
        split_pair(o4[0], o4[1], pk.x, pk.y);
        split_pair(o4[2], o4[3], pk.z, pk.w);
        *(uint4*)(As + rl * ASTRIDE + lane * 4) = pk;
    }
    __syncthreads();

    // GEMM1: H = gelu(A @ w1 + b1); warp covers n in [warp*32, warp*32+32)
    float acc1[4][4][4];
    #pragma unroll
    for (int mt = 0; mt < 4; mt++)
        #pragma unroll
        for (int nj = 0; nj < 4; nj++)
            #pragma unroll
            for (int q = 0; q < 4; q++) acc1[mt][nj][q] = 0.0f;

    #pragma unroll
    for (int ks = 0; ks < 8; ks++) {
        uint32_t ah[4][4], al[4][4];
        #pragma unroll
        for (int mt = 0; mt < 4; mt++) {
            const uint32_t* ap = As + (mt * 16 + lq) * ASTRIDE + (ks * 8 + lr) * 2;
            uint2 v0 = *(const uint2*)(ap);
            uint2 v1 = *(const uint2*)(ap + 8 * ASTRIDE);
            uint2 v2 = *(const uint2*)(ap + 8);
            uint2 v3 = *(const uint2*)(ap + 8 * ASTRIDE + 8);
            ah[mt][0] = v0.x; al[mt][0] = v0.y;
            ah[mt][1] = v1.x; al[mt][1] = v1.y;
            ah[mt][2] = v2.x; al[mt][2] = v2.y;
            ah[mt][3] = v3.x; al[mt][3] = v3.y;
        }
        #pragma unroll
        for (int nj = 0; nj < 4; nj++) {
            const uint32_t* bp = g_w1t + (warp * 32 + nj * 8 + lq) * 128 + (ks * 8 + lr) * 2;
            uint2 u0 = *(const uint2*)(bp);
            uint2 u1 = *(const uint2*)(bp + 8);
            uint32_t bh[2] = {u0.x, u1.x};
            uint32_t bl[2] = {u0.y, u1.y};
            #pragma unroll
            for (int mt = 0; mt < 4; mt++) {
                mma_bf16(acc1[mt][nj], ah[mt], bh);
                mma_bf16(acc1[mt][nj], ah[mt], bl);
                mma_bf16(acc1[mt][nj], al[mt], bh);
            }
        }
    }
    // bias + gelu, split into Hs
    #pragma unroll
    for (int nj = 0; nj < 4; nj++) {
        int n0 = warp * 32 + nj * 8 + lr * 2;
        float2 bb = *(const float2*)(b1 + n0);
        int pair = n0 >> 1;
        #pragma unroll
        for (int mt = 0; mt < 4; mt++) {
            int m0 = mt * 16 + lq;
            uint2 w0, w1v;
            split_pair(gelu_exact(acc1[mt][nj][0] + bb.x),
                       gelu_exact(acc1[mt][nj][1] + bb.y), w0.x, w0.y);
            split_pair(gelu_exact(acc1[mt][nj][2] + bb.x),
                       gelu_exact(acc1[mt][nj][3] + bb.y), w1v.x, w1v.y);
            *(uint2*)(Hs + m0 * HSTRIDE + pair * 2) = w0;
            *(uint2*)(Hs + (m0 + 8) * HSTRIDE + pair * 2) = w1v;
        }
    }
    __syncthreads();

    // GEMM2: out = x + H @ w2 + b2; warp covers n in [warp*16, warp*16+16); K=256
    float acc2[4][2][4];
    #pragma unroll
    for (int mt = 0; mt < 4; mt++)
        #pragma unroll
        for (int nj = 0; nj < 2; nj++)
            #pragma unroll
            for (int q = 0; q < 4; q++) acc2[mt][nj][q] = 0.0f;

    #pragma unroll
    for (int ks = 0; ks < 16; ks++) {
        uint32_t ah[4][4], al[4][4];
        #pragma unroll
        for (int mt = 0; mt < 4; mt++) {
            const uint32_t* ap = Hs + (mt * 16 + lq) * HSTRIDE + (ks * 8 + lr) * 2;
            uint2 v0 = *(const uint2*)(ap);
            uint2 v1 = *(const uint2*)(ap + 8 * HSTRIDE);
            uint2 v2 = *(const uint2*)(ap + 8);
            uint2 v3 = *(const uint2*)(ap + 8 * HSTRIDE + 8);
            ah[mt][0] = v0.x; al[mt][0] = v0.y;
            ah[mt][1] = v1.x; al[mt][1] = v1.y;
            ah[mt][2] = v2.x; al[mt][2] = v2.y;
            ah[mt][3] = v3.x; al[mt][3] = v3.y;
        }
        #pragma unroll
        for (int nj = 0; nj < 2; nj++) {
            const uint32_t* bp = g_w2t + (warp * 16 + nj * 8 + lq) * 256 + (ks * 8 + lr) * 2;
            uint2 u0 = *(const uint2*)(bp);
            uint2 u1 = *(const uint2*)(bp + 8);
            uint32_t bh[2] = {u0.x, u1.x};
            uint32_t bl[2] = {u0.y, u1.y};
            #pragma unroll
            for (int mt = 0; mt < 4; mt++) {
                mma_bf16(acc2[mt][nj], ah[mt], bh);
                mma_bf16(acc2[mt][nj], ah[mt], bl);
                mma_bf16(acc2[mt][nj], al[mt], bh);
            }
        }
    }
    // epilogue: bias + residual
    #pragma unroll
    for (int nj = 0; nj < 2; nj++) {
        int n0 = warp * 16 + nj * 8 + lr * 2;
        float2 bb = *(const float2*)(b2 + n0);
        #pragma unroll
        for (int mt = 0; mt < 4; mt++) {
            int m0 = mt * 16 + lq;
            {
                int gm = base + m0;
                float2 x = *(const float2*)(g_x + (size_t)gm * C + n0);
                float2 o;
                o.x = x.x + acc2[mt][nj][0] + bb.x;
                o.y = x.y + acc2[mt][nj][1] + bb.y;
                *(float2*)(out + (size_t)gm * C + n0) = o;
            }
            {
                int gm = base + m0 + 8;
                float2 x = *(const float2*)(g_x + (size_t)gm * C + n0);
                float2 o;
                o.x = x.x + acc2[mt][nj][2] + bb.x;
                o.y = x.y + acc2[mt][nj][3] + bb.y;
                *(float2*)(out + (size_t)gm * C + n0) = o;
            }
        }
    }
}

// ---------------- launch ----------------
extern "C" void kernel_launch(void* const* d_in, const int* in_sizes, int n_in,
                              void* d_out, int out_size)
{
    const float* xf    = (const float*)d_in[0];
    const int*   xi    = (const int*)  d_in[1];
    const float* t     = (const float*)d_in[2];
    const float* z     = (const float*)d_in[3];
    const float* nrm   = (const float*)d_in[4];
    const float* ln1w  = (const float*)d_in[5];
    const float* ln1b  = (const float*)d_in[6];
    const float* ln2w  = (const float*)d_in[7];
    const float* ln2b  = (const float*)d_in[8];
    const float* convw = (const float*)d_in[9];
    const float* t1w   = (const float*)d_in[10];
    const float* t1b   = (const float*)d_in[11];
    const float* t2w   = (const float*)d_in[12];
    const float* t2b   = (const float*)d_in[13];
    const float* z1w1  = (const float*)d_in[14];
    const float* z1b1  = (const float*)d_in[15];
    const float* z1w2  = (const float*)d_in[16];
    const float* z1b2  = (const float*)d_in[17];
    const float* z2w1  = (const float*)d_in[18];
    const float* z2b1  = (const float*)d_in[19];
    const float* z2w2  = (const float*)d_in[20];
    const float* z2b2  = (const float*)d_in[21];
    const float* w1    = (const float*)d_in[22];
    const float* b1    = (const float*)d_in[23];
    const float* w2    = (const float*)d_in[24];
    const float* b2    = (const float*)d_in[25];
    float* out = (float*)d_out;

    const int CONV_SMEM = 2 * 128 * ASTRIDE * 4;               // 139264
    const int MLP_SMEM  = (64 * ASTRIDE + 64 * HSTRIDE) * 4;   // 102400
    cudaFuncSetAttribute(conv_kernel, cudaFuncAttributeMaxDynamicSharedMemorySize, CONV_SMEM);
    cudaFuncSetAttribute(mlp_kernel,  cudaFuncAttributeMaxDynamicSharedMemorySize, MLP_SMEM);

    fill_grid_kernel<<<(NBATCH * IMG * IMG) / 256, 256>>>();
    scatter_grid_kernel<<<NPTS / 256, 256>>>(xi);

    dim3 mg(NBATCH, 2);
    modvec_kernel<<<mg, 256>>>(t, z, t1w, t1b, t2w, t2b,
                               z1w1, z1b1, z1w2, z1b2,
                               z2w1, z2b1, z2w2, z2b2);

    split_weights_kernel<<<(NCONVP + NW1P + NW2P) / 256, 256>>>(convw, w1, w2);

    modulate1_kernel<<<NPTS / 8, 256>>>(xf, ln1w, ln1b);

    conv_kernel<<<NPTS / 128, 256, CONV_SMEM>>>(xf, nrm, xi);

    mlp_kernel<<<NPTS / 64, 256, MLP_SMEM>>>(ln2w, ln2b, b1, b2, out);

    (void)in_sizes; (void)n_in; (void)out_size;
}

// round 6
// speedup vs baseline: 1.6024x; 1.2000x over previous
#include <cuda_runtime.h>
#include <cuda_bf16.h>
#include <math.h>
#include <stdint.h>

#define NBATCH 4
#define IMG    256
#define C      128
#define ACTPTS 32768
#define NPTS   (NBATCH*ACTPTS)
#define TD     512
#define ZD     256
#define LN_EPS 1e-5f

__device__ uint32_t g_h1p[(size_t)NPTS * 128];   // modulated input, {hi,lo} bf16x2 pair-words
__device__ float    g_x [(size_t)NPTS * C];
__device__ int      g_grid[NBATCH * IMG * IMG];
__device__ float g_tt1[NBATCH*2*C], g_tt2[NBATCH*2*C], g_zz1[NBATCH*C], g_zz2[NBATCH*C];
__device__ uint32_t g_wct[49 * 128 * 128];       // conv w^T: [tap][cout][128 pair-words]
__device__ uint32_t g_w1t[256 * 128];
__device__ uint32_t g_w2t[128 * 256];

__device__ __forceinline__ float gelu_exact(float x) {
    return 0.5f * x * (1.0f + erff(x * 0.70710678118654752440f));
}
__device__ __forceinline__ void split_pair(float a, float b, uint32_t& hi, uint32_t& lo) {
    __nv_bfloat16 ha = __float2bfloat16_rn(a), hb = __float2bfloat16_rn(b);
    __nv_bfloat16 la = __float2bfloat16_rn(a - __bfloat162float(ha));
    __nv_bfloat16 lb = __float2bfloat16_rn(b - __bfloat162float(hb));
    hi = (uint32_t)__bfloat16_as_ushort(ha) | ((uint32_t)__bfloat16_as_ushort(hb) << 16);
    lo = (uint32_t)__bfloat16_as_ushort(la) | ((uint32_t)__bfloat16_as_ushort(lb) << 16);
}
__device__ __forceinline__ void mma_bf16(float* d, const uint32_t* a, const uint32_t* b) {
    asm volatile("mma.sync.aligned.m16n8k16.row.col.f32.bf16.bf16.f32 "
        "{%0,%1,%2,%3},{%4,%5,%6,%7},{%8,%9},{%0,%1,%2,%3};\n"
        : "+f"(d[0]), "+f"(d[1]), "+f"(d[2]), "+f"(d[3])
        : "r"(a[0]), "r"(a[1]), "r"(a[2]), "r"(a[3]), "r"(b[0]), "r"(b[1]));
}
__device__ __forceinline__ uint32_t smem_u32(const void* p) {
    uint32_t a;
    asm("{ .reg .u64 t; cvta.to.shared.u64 t, %1; cvt.u32.u64 %0, t; }" : "=r"(a) : "l"(p));
    return a;
}
__device__ __forceinline__ void cp16(uint32_t dst, const void* src, uint32_t srcsize) {
    asm volatile("cp.async.ca.shared.global [%0], [%1], 16, %2;"
                 :: "r"(dst), "l"(src), "r"(srcsize) : "memory");
}
#define CP_COMMIT() asm volatile("cp.async.commit_group;" ::: "memory")
#define CP_WAIT1()  asm volatile("cp.async.wait_group 1;" ::: "memory")
#define CP_WAIT0()  asm volatile("cp.async.wait_group 0;" ::: "memory")

__global__ void fill_grid_kernel() { g_grid[blockIdx.x * 256 + threadIdx.x] = -1; }
__global__ void scatter_grid_kernel(const int* __restrict__ xidx) {
    int n = blockIdx.x * 256 + threadIdx.x;
    g_grid[(xidx[3*n] << 16) | (xidx[3*n+1] << 8) | xidx[3*n+2]] = n;
}

#define NCONVP (49*128*64)
#define NW1P   (256*64)
#define NW2P   (128*128)
__global__ void split_weights_kernel(const float* __restrict__ convw,
                                     const float* __restrict__ w1, const float* __restrict__ w2) {
    int i = blockIdx.x * 256 + threadIdx.x;
    uint32_t hi, lo;
    if (i < NCONVP) {
        int p = i & 63, rest = i >> 6;
        int cout = rest & 127, tap = rest >> 7;
        split_pair(convw[(tap*128 + 2*p + 0)*128 + cout], convw[(tap*128 + 2*p + 1)*128 + cout], hi, lo);
        g_wct[(tap*128 + cout)*128 + p*2]     = hi;
        g_wct[(tap*128 + cout)*128 + p*2 + 1] = lo;
    } else if (i < NCONVP + NW1P) {
        int j = i - NCONVP, p = j & 63, n = j >> 6;
        split_pair(w1[(2*p+0)*256 + n], w1[(2*p+1)*256 + n], hi, lo);
        g_w1t[n*128 + p*2] = hi; g_w1t[n*128 + p*2 + 1] = lo;
    } else {
        int j = i - (NCONVP + NW1P), p = j & 127, n = j >> 7;
        split_pair(w2[(2*p+0)*128 + n], w2[(2*p+1)*128 + n], hi, lo);
        g_w2t[n*256 + p*2] = hi; g_w2t[n*256 + p*2 + 1] = lo;
    }
}

__global__ void modvec_kernel(
    const float* __restrict__ t,   const float* __restrict__ z,
    const float* __restrict__ t1w, const float* __restrict__ t1b,
    const float* __restrict__ t2w, const float* __restrict__ t2b,
    const float* __restrict__ z1w1, const float* __restrict__ z1b1,
    const float* __restrict__ z1w2, const float* __restrict__ z1b2,
    const float* __restrict__ z2w1, const float* __restrict__ z2b1,
    const float* __restrict__ z2w2, const float* __restrict__ z2b2) {
    const int b = blockIdx.x, tid = threadIdx.x;
    if (blockIdx.y == 0) {
        __shared__ float gt[TD];
        gt[tid] = gelu_exact(t[b*TD + tid]);
        gt[tid + 256] = gelu_exact(t[b*TD + tid + 256]);
        __syncthreads();
        float a1 = t1b[tid], a2 = t2b[tid];
        #pragma unroll 8
        for (int k = 0; k < TD; k++) { float g = gt[k]; a1 += g*t1w[k*256+tid]; a2 += g*t2w[k*256+tid]; }
        g_tt1[b*256 + tid] = a1; g_tt2[b*256 + tid] = a2;
    } else {
        __shared__ float gz[ZD], hz[2*C];
        gz[tid] = z[b*ZD + tid];
        __syncthreads();
        {
            int j = tid & 127;
            const float* w = (tid < 128) ? z1w1 : z2w1;
            const float* bb = (tid < 128) ? z1b1 : z2b1;
            float a = bb[j];
            #pragma unroll 8
            for (int k = 0; k < ZD; k++) a += gz[k] * w[k*C + j];
            hz[tid] = gelu_exact(a);
        }
        __syncthreads();
        {
            int j = tid & 127;
            const float* w = (tid < 128) ? z1w2 : z2w2;
            const float* bb = (tid < 128) ? z1b2 : z2b2;
            const float* h = (tid < 128) ? hz : (hz + C);
            float a = bb[j];
            #pragma unroll 8
            for (int k = 0; k < C; k++) a += h[k] * w[k*C + j];
            if (tid < 128) g_zz1[b*C + j] = a; else g_zz2[b*C + j] = a;
        }
    }
}

__global__ void modulate1_kernel(const float* __restrict__ xf,
                                 const float* __restrict__ lnw, const float* __restrict__ lnb) {
    const int warp = threadIdx.x >> 5, lane = threadIdx.x & 31;
    const int n = blockIdx.x * 8 + warp, b = n >> 15;
    float4 v = *(const float4*)(xf + (size_t)n*C + lane*4);
    float s = v.x + v.y + v.z + v.w;
    float sq = v.x*v.x + v.y*v.y + v.z*v.z + v.w*v.w;
    #pragma unroll
    for (int o = 16; o; o >>= 1) {
        s  += __shfl_xor_sync(0xffffffffu, s,  o);
        sq += __shfl_xor_sync(0xffffffffu, sq, o);
    }
    float mu = s * (1.0f/C);
    float rs = rsqrtf(sq*(1.0f/C) - mu*mu + LN_EPS);
    float vv[4] = {v.x, v.y, v.z, v.w}, o4[4];
    #pragma unroll
    for (int u = 0; u < 4; u++) {
        int c = lane*4 + u;
        float f = (vv[u] - mu)*rs*lnw[c] + lnb[c];
        f = f*(1.0f + g_tt1[b*256 + c]) + g_tt1[b*256 + 128 + c];
        o4[u] = f*(1.0f + g_zz1[b*128 + c]);
    }
    uint4 pk;
    split_pair(o4[0], o4[1], pk.x, pk.y);
    split_pair(o4[2], o4[3], pk.z, pk.w);
    *(uint4*)(g_h1p + (size_t)n*128 + lane*4) = pk;
}

// ---------------- conv: cp.async double-buffered split-bf16 mma.sync GEMM ----------------
// CTA: 128 points x 128 couts, 256 threads, 8 warps (wm 0..3 x wn 0..1), warp tile m32 x n64.
// 98 chunks (49 taps x 2 cin-halves of 64). Chunk buffer: A 128x272B + B 128x272B.
#define CHSTRIDE 68                    // words per chunk row (64 data + 4 pad)
#define CHUNKB   (128 * CHSTRIDE * 4)  // 34816 B
#define BUFBYTES (2 * CHUNKB)          // 69632 B (A + B)
#define CONV_SMEM (2 * BUFBYTES)       // 139264 B
__device__ __forceinline__ int nbr_lookup(int myb, int myy, int myx, int tap) {
    int ny = myy + tap/7 - 3, nx = myx + tap%7 - 3;
    if ((unsigned)ny < 256u && (unsigned)nx < 256u) return g_grid[myb | (ny<<8) | nx];
    return -1;
}
__device__ __forceinline__ void stage_chunk(uint32_t Ab, uint32_t Bb, int tap, int ch,
                                            int nbr, int row, int hh) {
    const char* asrc = (const char*)g_h1p;
    uint32_t sz = 0;
    if (nbr >= 0) { asrc += (size_t)nbr*512 + ch*256 + hh*128; sz = 16; }
    uint32_t adst = Ab + row*272 + hh*128;
    #pragma unroll
    for (int j = 0; j < 8; j++) cp16(adst + j*16, asrc + j*16, sz);
    const char* bsrc = (const char*)g_wct + (size_t)(tap*128 + row)*512 + ch*256 + hh*128;
    uint32_t bdst = Bb + row*272 + hh*128;
    #pragma unroll
    for (int j = 0; j < 8; j++) cp16(bdst + j*16, bsrc + j*16, 16);
}

__global__ __launch_bounds__(256, 1) void conv_kernel(
    const float* __restrict__ xf, const float* __restrict__ nrm, const int* __restrict__ xidx) {
    extern __shared__ uint8_t smemraw[];
    const uint32_t sb32 = smem_u32(smemraw);
    const int tid = threadIdx.x, warp = tid >> 5, lane = tid & 31;
    const int wm = warp >> 1, wn = warp & 1;
    const int lq = lane >> 2, lr = lane & 3;
    const int base = blockIdx.x * 128;
    const int row = tid >> 1, hh = tid & 1;

    const int n0i = base + row;
    const int myb = xidx[3*n0i] << 16, myy = xidx[3*n0i+1], myx = xidx[3*n0i+2];

    float acc[2][8][4];
    #pragma unroll
    for (int mt = 0; mt < 2; mt++)
        #pragma unroll
        for (int nj = 0; nj < 8; nj++)
            #pragma unroll
            for (int q = 0; q < 4; q++) acc[mt][nj][q] = 0.0f;

    const uint32_t AbU[2] = { sb32, sb32 + BUFBYTES };
    const uint32_t BbU[2] = { sb32 + CHUNKB, sb32 + BUFBYTES + CHUNKB };

    int nbr_s = nbr_lookup(myb, myy, myx, 0);
    int nbr_p = -1;
    stage_chunk(AbU[0], BbU[0], 0, 0, nbr_s, row, hh);
    CP_COMMIT();

    #pragma unroll 2
    for (int c = 0; c < 98; c++) {
        const int tap = c >> 1;
        if (c < 97) {
            const int c1 = c + 1;
            int nbr_use = (c1 & 1) ? nbr_s : nbr_p;
            if ((c1 & 1) == 0) nbr_s = nbr_p;
            stage_chunk(AbU[c1 & 1], BbU[c1 & 1], c1 >> 1, c1 & 1, nbr_use, row, hh);
            CP_COMMIT();
            CP_WAIT1();
        } else {
            CP_WAIT0();
        }
        __syncthreads();
        if ((c & 1) == 0 && tap + 1 < 49)
            nbr_p = nbr_lookup(myb, myy, myx, tap + 1);   // prefetch, hidden under MMA

        const uint32_t* As = (const uint32_t*)(smemraw + (c & 1) * BUFBYTES);
        const uint32_t* Bs = (const uint32_t*)(smemraw + (c & 1) * BUFBYTES + CHUNKB);
        #pragma unroll
        for (int ks = 0; ks < 4; ks++) {
            uint32_t ah[2][4], al[2][4];
            #pragma unroll
            for (int mt = 0; mt < 2; mt++) {
                const uint32_t* ap = As + (wm*32 + mt*16 + lq)*CHSTRIDE + (ks*8 + lr)*2;
                uint2 v0 = *(const uint2*)(ap);
                uint2 v1 = *(const uint2*)(ap + 8*CHSTRIDE);
                uint2 v2 = *(const uint2*)(ap + 8);
                uint2 v3 = *(const uint2*)(ap + 8*CHSTRIDE + 8);
                ah[mt][0]=v0.x; al[mt][0]=v0.y; ah[mt][1]=v1.x; al[mt][1]=v1.y;
                ah[mt][2]=v2.x; al[mt][2]=v2.y; ah[mt][3]=v3.x; al[mt][3]=v3.y;
            }
            #pragma unroll
            for (int nj = 0; nj < 8; nj++) {
                const uint32_t* bp = Bs + (wn*64 + nj*8 + lq)*CHSTRIDE + (ks*8 + lr)*2;
                uint2 u0 = *(const uint2*)(bp);
                uint2 u1 = *(const uint2*)(bp + 8);
                uint32_t bh[2] = {u0.x, u1.x}, bl[2] = {u0.y, u1.y};
                #pragma unroll
                for (int mt = 0; mt < 2; mt++) {
                    mma_bf16(acc[mt][nj], ah[mt], bh);
                    mma_bf16(acc[mt][nj], ah[mt], bl);
                    mma_bf16(acc[mt][nj], al[mt], bh);
                }
            }
        }
        __syncthreads();
    }

    // epilogue: x = x_features + conv/norm
    #pragma unroll
    for (int mt = 0; mt < 2; mt++) {
        int m = wm*32 + mt*16 + lq;
        float inv0 = 1.0f / nrm[base + m];
        float inv8 = 1.0f / nrm[base + m + 8];
        #pragma unroll
        for (int nj = 0; nj < 8; nj++) {
            int nn = wn*64 + nj*8 + lr*2;
            int gm = base + m;
            float2 x0 = *(const float2*)(xf + (size_t)gm*C + nn);
            float2 o0 = { x0.x + acc[mt][nj][0]*inv0, x0.y + acc[mt][nj][1]*inv0 };
            *(float2*)(g_x + (size_t)gm*C + nn) = o0;
            gm += 8;
            float2 x1 = *(const float2*)(xf + (size_t)gm*C + nn);
            float2 o1 = { x1.x + acc[mt][nj][2]*inv8, x1.y + acc[mt][nj][3]*inv8 };
            *(float2*)(g_x + (size_t)gm*C + nn) = o1;
        }
    }
}

// ---------------- stage-2: LN2 + modulation + MLP + residual (validated path) --------
#define ASTRIDE 136
#define HSTRIDE 264
__global__ __launch_bounds__(256) void mlp_kernel(
    const float* __restrict__ lnw, const float* __restrict__ lnb,
    const float* __restrict__ b1,  const float* __restrict__ b2, float* __restrict__ out) {
    extern __shared__ uint32_t smem[];
    uint32_t* As = smem;
    uint32_t* Hs = smem + 64 * ASTRIDE;
    const int tid = threadIdx.x, warp = tid >> 5, lane = tid & 31;
    const int lq = lane >> 2, lr = lane & 3;
    const int base = blockIdx.x * 64;

    #pragma unroll
    for (int rr = 0; rr < 8; rr++) {
        int rl = warp*8 + rr, n = base + rl, b = n >> 15;
        float4 v = *(const float4*)(g_x + (size_t)n*C + lane*4);
        float s = v.x+v.y+v.z+v.w, sq = v.x*v.x+v.y*v.y+v.z*v.z+v.w*v.w;
        #pragma unroll
        for (int o = 16; o; o >>= 1) {
            s  += __shfl_xor_sync(0xffffffffu, s,  o);
            sq += __shfl_xor_sync(0xffffffffu, sq, o);
        }
        float mu = s*(1.0f/C), rs = rsqrtf(sq*(1.0f/C) - mu*mu + LN_EPS);
        float vv[4] = {v.x,v.y,v.z,v.w}, o4[4];
        #pragma unroll
        for (int u = 0; u < 4; u++) {
            int c = lane*4 + u;
            float f = (vv[u]-mu)*rs*lnw[c] + lnb[c];
            f = f*(1.0f + g_tt2[b*256+c]) + g_tt2[b*256+128+c];
            o4[u] = f*(1.0f + g_zz2[b*128+c]);
        }
        uint4 pk;
        split_pair(o4[0], o4[1], pk.x, pk.y);
        split_pair(o4[2], o4[3], pk.z, pk.w);
        *(uint4*)(As + rl*ASTRIDE + lane*4) = pk;
    }
    __syncthreads();

    float acc1[4][4][4];
    #pragma unroll
    for (int mt = 0; mt < 4; mt++)
        #pragma unroll
        for (int nj = 0; nj < 4; nj++)
            #pragma unroll
            for (int q = 0; q < 4; q++) acc1[mt][nj][q] = 0.0f;
    #pragma unroll
    for (int ks = 0; ks < 8; ks++) {
        uint32_t ah[4][4], al[4][4];
        #pragma unroll
        for (int mt = 0; mt < 4; mt++) {
            const uint32_t* ap = As + (mt*16 + lq)*ASTRIDE + (ks*8 + lr)*2;
            uint2 v0 = *(const uint2*)(ap), v1 = *(const uint2*)(ap + 8*ASTRIDE);
            uint2 v2 = *(const uint2*)(ap + 8), v3 = *(const uint2*)(ap + 8*ASTRIDE + 8);
            ah[mt][0]=v0.x; al[mt][0]=v0.y; ah[mt][1]=v1.x; al[mt][1]=v1.y;
            ah[mt][2]=v2.x; al[mt][2]=v2.y; ah[mt][3]=v3.x; al[mt][3]=v3.y;
        }
        #pragma unroll
        for (int nj = 0; nj < 4; nj++) {
            const uint32_t* bp = g_w1t + (warp*32 + nj*8 + lq)*128 + (ks*8 + lr)*2;
            uint2 u0 = *(const uint2*)(bp), u1 = *(const uint2*)(bp + 8);
            uint32_t bh[2] = {u0.x, u1.x}, bl[2] = {u0.y, u1.y};
            #pragma unroll
            for (int mt = 0; mt < 4; mt++) {
                mma_bf16(acc1[mt][nj], ah[mt], bh);
                mma_bf16(acc1[mt][nj], ah[mt], bl);
                mma_bf16(acc1[mt][nj], al[mt], bh);
            }
        }
    }
    #pragma unroll
    for (int nj = 0; nj < 4; nj++) {
        int nn = warp*32 + nj*8 + lr*2;
        float2 bb = *(const float2*)(b1 + nn);
        int pair = nn >> 1;
        #pragma unroll
        for (int mt = 0; mt < 4; mt++) {
            int m0 = mt*16 + lq;
            uint2 w0, w1v;
            split_pair(gelu_exact(acc1[mt][nj][0]+bb.x), gelu_exact(acc1[mt][nj][1]+bb.y), w0.x, w0.y);
            split_pair(gelu_exact(acc1[mt][nj][2]+bb.x), gelu_exact(acc1[mt][nj][3]+bb.y), w1v.x, w1v.y);
            *(uint2*)(Hs + m0*HSTRIDE + pair*2) = w0;
            *(uint2*)(Hs + (m0+8)*HSTRIDE + pair*2) = w1v;
        }
    }
    __syncthreads();

    float acc2[4][2][4];
    #pragma unroll
    for (int mt = 0; mt < 4; mt++)
        #pragma unroll
        for (int nj = 0; nj < 2; nj++)
            #pragma unroll
            for (int q = 0; q < 4; q++) acc2[mt][nj][q] = 0.0f;
    #pragma unroll
    for (int ks = 0; ks < 16; ks++) {
        uint32_t ah[4][4], al[4][4];
        #pragma unroll
        for (int mt = 0; mt < 4; mt++) {
            const uint32_t* ap = Hs + (mt*16 + lq)*HSTRIDE + (ks*8 + lr)*2;
            uint2 v0 = *(const uint2*)(ap), v1 = *(const uint2*)(ap + 8*HSTRIDE);
            uint2 v2 = *(const uint2*)(ap + 8), v3 = *(const uint2*)(ap + 8*HSTRIDE + 8);
            ah[mt][0]=v0.x; al[mt][0]=v0.y; ah[mt][1]=v1.x; al[mt][1]=v1.y;
            ah[mt][2]=v2.x; al[mt][2]=v2.y; ah[mt][3]=v3.x; al[mt][3]=v3.y;
        }
        #pragma unroll
        for (int nj = 0; nj < 2; nj++) {
            const uint32_t* bp = g_w2t + (warp*16 + nj*8 + lq)*256 + (ks*8 + lr)*2;
            uint2 u0 = *(const uint2*)(bp), u1 = *(const uint2*)(bp + 8);
            uint32_t bh[2] = {u0.x, u1.x}, bl[2] = {u0.y, u1.y};
            #pragma unroll
            for (int mt = 0; mt < 4; mt++) {
                mma_bf16(acc2[mt][nj], ah[mt], bh);
                mma_bf16(acc2[mt][nj], ah[mt], bl);
                mma_bf16(acc2[mt][nj], al[mt], bh);
            }
        }
    }
    #pragma unroll
    for (int nj = 0; nj < 2; nj++) {
        int nn = warp*16 + nj*8 + lr*2;
        float2 bb = *(const float2*)(b2 + nn);
        #pragma unroll
        for (int mt = 0; mt < 4; mt++) {
            int m0 = mt*16 + lq;
            int gm = base + m0;
            float2 x = *(const float2*)(g_x + (size_t)gm*C + nn);
            float2 o = { x.x + acc2[mt][nj][0] + bb.x, x.y + acc2[mt][nj][1] + bb.y };
            *(float2*)(out + (size_t)gm*C + nn) = o;
            gm += 8;
            x = *(const float2*)(g_x + (size_t)gm*C + nn);
            o.x = x.x + acc2[mt][nj][2] + bb.x;
            o.y = x.y + acc2[mt][nj][3] + bb.y;
            *(float2*)(out + (size_t)gm*C + nn) = o;
        }
    }
}

extern "C" void kernel_launch(void* const* d_in, const int* in_sizes, int n_in,
                              void* d_out, int out_size) {
    const float* xf    = (const float*)d_in[0];
    const int*   xi    = (const int*)  d_in[1];
    const float* t     = (const float*)d_in[2];
    const float* z     = (const float*)d_in[3];
    const float* nrm   = (const float*)d_in[4];
    const float* ln1w  = (const float*)d_in[5];
    const float* ln1b  = (const float*)d_in[6];
    const float* ln2w  = (const float*)d_in[7];
    const float* ln2b  = (const float*)d_in[8];
    const float* convw = (const float*)d_in[9];
    const float* t1w   = (const float*)d_in[10];
    const float* t1b   = (const float*)d_in[11];
    const float* t2w   = (const float*)d_in[12];
    const float* t2b   = (const float*)d_in[13];
    const float* z1w1  = (const float*)d_in[14];
    const float* z1b1  = (const float*)d_in[15];
    const float* z1w2  = (const float*)d_in[16];
    const float* z1b2  = (const float*)d_in[17];
    const float* z2w1  = (const float*)d_in[18];
    const float* z2b1  = (const float*)d_in[19];
    const float* z2w2  = (const float*)d_in[20];
    const float* z2b2  = (const float*)d_in[21];
    const float* w1    = (const float*)d_in[22];
    const float* b1    = (const float*)d_in[23];
    const float* w2    = (const float*)d_in[24];
    const float* b2    = (const float*)d_in[25];
    float* out = (float*)d_out;

    const int MLP_SMEM = (64*ASTRIDE + 64*HSTRIDE) * 4;
    cudaFuncSetAttribute(conv_kernel, cudaFuncAttributeMaxDynamicSharedMemorySize, CONV_SMEM);
    cudaFuncSetAttribute(mlp_kernel,  cudaFuncAttributeMaxDynamicSharedMemorySize, MLP_SMEM);

    fill_grid_kernel<<<(NBATCH*IMG*IMG)/256, 256>>>();
    scatter_grid_kernel<<<NPTS/256, 256>>>(xi);
    dim3 mg(NBATCH, 2);
    modvec_kernel<<<mg, 256>>>(t, z, t1w, t1b, t2w, t2b,
                               z1w1, z1b1, z1w2, z1b2, z2w1, z2b1, z2w2, z2b2);
    split_weights_kernel<<<(NCONVP + NW1P + NW2P)/256, 256>>>(convw, w1, w2);
    modulate1_kernel<<<NPTS/8, 256>>>(xf, ln1w, ln1b);
    conv_kernel<<<NPTS/128, 256, CONV_SMEM>>>(xf, nrm, xi);
    mlp_kernel<<<NPTS/64, 256, MLP_SMEM>>>(ln2w, ln2b, b1, b2, out);
    (void)in_sizes; (void)n_in; (void)out_size;
}

// round 8
// speedup vs baseline: 2.3280x; 1.4528x over previous
#include <cuda_runtime.h>
#include <cuda_fp16.h>
#include <math.h>
#include <stdint.h>

#define NBATCH 4
#define IMG    256
#define C      128
#define ACTPTS 32768
#define NPTS   (NBATCH*ACTPTS)
#define TD     512
#define ZD     256
#define LN_EPS 1e-5f

__device__ uint32_t g_h1f[(size_t)NPTS * 64];    // modulated input, fp16x2 words (32 MB)
__device__ float    g_x [(size_t)NPTS * C];
__device__ int      g_grid[NBATCH * IMG * IMG];
__device__ float g_tt1[NBATCH*2*C], g_tt2[NBATCH*2*C], g_zz1[NBATCH*C], g_zz2[NBATCH*C];
__device__ uint32_t g_wct[49 * 128 * 128];       // conv w^T: [tap][cout][128 words {wh,wl}/k-pair]
__device__ uint32_t g_w1t[256 * 128];            // w1^T fp16 {wh,wl} pair-words
__device__ uint32_t g_w2t[128 * 256];

__device__ __forceinline__ float gelu_exact(float x) {
    return 0.5f * x * (1.0f + erff(x * 0.70710678118654752440f));
}
__device__ __forceinline__ uint32_t pack_h2(float a, float b) {
    __half2 h = __floats2half2_rn(a, b);
    return *(uint32_t*)&h;
}
__device__ __forceinline__ void split16(float a, float b, uint32_t& hi, uint32_t& lo) {
    __half ha = __float2half_rn(a), hb = __float2half_rn(b);
    __half la = __float2half_rn(a - __half2float(ha));
    __half lb = __float2half_rn(b - __half2float(hb));
    hi = (uint32_t)__half_as_ushort(ha) | ((uint32_t)__half_as_ushort(hb) << 16);
    lo = (uint32_t)__half_as_ushort(la) | ((uint32_t)__half_as_ushort(lb) << 16);
}
__device__ __forceinline__ void mma_f16(float* d, const uint32_t* a, const uint32_t* b) {
    asm volatile("mma.sync.aligned.m16n8k16.row.col.f32.f16.f16.f32 "
        "{%0,%1,%2,%3},{%4,%5,%6,%7},{%8,%9},{%0,%1,%2,%3};\n"
        : "+f"(d[0]), "+f"(d[1]), "+f"(d[2]), "+f"(d[3])
        : "r"(a[0]), "r"(a[1]), "r"(a[2]), "r"(a[3]), "r"(b[0]), "r"(b[1]));
}
__device__ __forceinline__ uint32_t smem_u32(const void* p) {
    uint32_t a;
    asm("{ .reg .u64 t; cvta.to.shared.u64 t, %1; cvt.u32.u64 %0, t; }" : "=r"(a) : "l"(p));
    return a;
}
__device__ __forceinline__ void cp16(uint32_t dst, const void* src, uint32_t srcsize) {
    asm volatile("cp.async.ca.shared.global [%0], [%1], 16, %2;"
                 :: "r"(dst), "l"(src), "r"(srcsize) : "memory");
}
#define CP_COMMIT() asm volatile("cp.async.commit_group;" ::: "memory")
#define CP_WAIT1()  asm volatile("cp.async.wait_group 1;" ::: "memory")
#define CP_WAIT0()  asm volatile("cp.async.wait_group 0;" ::: "memory")

// ---------------- launch 1: grid fill ----------------
__global__ void fill_grid_kernel() { g_grid[blockIdx.x * 256 + threadIdx.x] = -1; }

// ---------------- launch 2: fused init (scatter + modvec + weight split) ------------
#define NCONVP (49*128*64)
#define NW1P   (256*64)
#define NW2P   (128*128)
#define SPLIT_BLKS ((NCONVP + NW1P + NW2P) / 256)   // 1696
__global__ void fused_init_kernel(
    const int* __restrict__ xidx,
    const float* __restrict__ t,   const float* __restrict__ z,
    const float* __restrict__ t1w, const float* __restrict__ t1b,
    const float* __restrict__ t2w, const float* __restrict__ t2b,
    const float* __restrict__ z1w1, const float* __restrict__ z1b1,
    const float* __restrict__ z1w2, const float* __restrict__ z1b2,
    const float* __restrict__ z2w1, const float* __restrict__ z2b1,
    const float* __restrict__ z2w2, const float* __restrict__ z2b2,
    const float* __restrict__ convw, const float* __restrict__ w1, const float* __restrict__ w2)
{
    const int bid = blockIdx.x, tid = threadIdx.x;
    __shared__ float sbuf[768];
    if (bid < 512) {                       // scatter
        int n = bid * 256 + tid;
        g_grid[(xidx[3*n] << 16) | (xidx[3*n+1] << 8) | xidx[3*n+2]] = n;
    } else if (bid < 520) {                // modvec
        const int b = (bid - 512) >> 1;
        if (((bid - 512) & 1) == 0) {
            float* gt = sbuf;
            gt[tid] = gelu_exact(t[b*TD + tid]);
            gt[tid + 256] = gelu_exact(t[b*TD + tid + 256]);
            __syncthreads();
            float a1 = t1b[tid], a2 = t2b[tid];
            #pragma unroll 8
            for (int k = 0; k < TD; k++) { float g = gt[k]; a1 += g*t1w[k*256+tid]; a2 += g*t2w[k*256+tid]; }
            g_tt1[b*256 + tid] = a1; g_tt2[b*256 + tid] = a2;
        } else {
            float* gz = sbuf; float* hz = sbuf + 256;
            gz[tid] = z[b*ZD + tid];
            __syncthreads();
            {
                int j = tid & 127;
                const float* w = (tid < 128) ? z1w1 : z2w1;
                const float* bb = (tid < 128) ? z1b1 : z2b1;
                float a = bb[j];
                #pragma unroll 8
                for (int k = 0; k < ZD; k++) a += gz[k] * w[k*C + j];
                hz[tid] = gelu_exact(a);
            }
            __syncthreads();
            {
                int j = tid & 127;
                const float* w = (tid < 128) ? z1w2 : z2w2;
                const float* bb = (tid < 128) ? z1b2 : z2b2;
                const float* h = (tid < 128) ? hz : (hz + C);
                float a = bb[j];
                #pragma unroll 8
                for (int k = 0; k < C; k++) a += h[k] * w[k*C + j];
                if (tid < 128) g_zz1[b*C + j] = a; else g_zz2[b*C + j] = a;
            }
        }
    } else {                               // weight split (fp16 hi/lo)
        int i = (bid - 520) * 256 + tid;
        uint32_t hi, lo;
        if (i < NCONVP) {
            int p = i & 63, rest = i >> 6;
            int cout = rest & 127, tap = rest >> 7;
            split16(convw[(tap*128 + 2*p + 0)*128 + cout], convw[(tap*128 + 2*p + 1)*128 + cout], hi, lo);
            g_wct[(tap*128 + cout)*128 + p*2]     = hi;
            g_wct[(tap*128 + cout)*128 + p*2 + 1] = lo;
        } else if (i < NCONVP + NW1P) {
            int j = i - NCONVP, p = j & 63, n = j >> 6;
            split16(w1[(2*p+0)*256 + n], w1[(2*p+1)*256 + n], hi, lo);
            g_w1t[n*128 + p*2] = hi; g_w1t[n*128 + p*2 + 1] = lo;
        } else {
            int j = i - (NCONVP + NW1P), p = j & 127, n = j >> 7;
            split16(w2[(2*p+0)*128 + n], w2[(2*p+1)*128 + n], hi, lo);
            g_w2t[n*256 + p*2] = hi; g_w2t[n*256 + p*2 + 1] = lo;
        }
    }
}

// ---------------- launch 3: LN1 + modulation -> single fp16 plane ----------------
__global__ void modulate1_kernel(const float* __restrict__ xf,
                                 const float* __restrict__ lnw, const float* __restrict__ lnb) {
    const int warp = threadIdx.x >> 5, lane = threadIdx.x & 31;
    const int n = blockIdx.x * 8 + warp, b = n >> 15;
    float4 v = *(const float4*)(xf + (size_t)n*C + lane*4);
    float s = v.x + v.y + v.z + v.w;
    float sq = v.x*v.x + v.y*v.y + v.z*v.z + v.w*v.w;
    #pragma unroll
    for (int o = 16; o; o >>= 1) {
        s  += __shfl_xor_sync(0xffffffffu, s,  o);
        sq += __shfl_xor_sync(0xffffffffu, sq, o);
    }
    float mu = s * (1.0f/C);
    float rs = rsqrtf(sq*(1.0f/C) - mu*mu + LN_EPS);
    float vv[4] = {v.x, v.y, v.z, v.w}, o4[4];
    #pragma unroll
    for (int u = 0; u < 4; u++) {
        int c = lane*4 + u;
        float f = (vv[u] - mu)*rs*lnw[c] + lnb[c];
        f = f*(1.0f + g_tt1[b*256 + c]) + g_tt1[b*256 + 128 + c];
        o4[u] = f*(1.0f + g_zz1[b*128 + c]);
    }
    uint2 pk = { pack_h2(o4[0], o4[1]), pack_h2(o4[2], o4[3]) };
    *(uint2*)(g_h1f + (size_t)n*64 + lane*2) = pk;
}

// ---------------- launch 4: conv (2-pass split-fp16, cp.async double-buffer) --------
#define AST 36                           // A chunk row stride (words); 32 data words
#define ACHUNK (128*AST*4)               // 18432 B
#define BST 68                           // B chunk row stride (words); 64 data words
#define BCHUNK (128*BST*4)               // 34816 B
#define BUFB (ACHUNK + BCHUNK)           // 53248 B
#define CONV_SMEM (2*BUFB)               // 106496 B
__device__ __forceinline__ int nbr_lookup(int myb, int myy, int myx, int tap) {
    int ny = myy + tap/7 - 3, nx = myx + tap%7 - 3;
    if ((unsigned)ny < 256u && (unsigned)nx < 256u) return g_grid[myb | (ny<<8) | nx];
    return -1;
}
__device__ __forceinline__ void stage_chunk(uint32_t Ab, uint32_t Bb, int tap, int ch,
                                            int nbr, int row, int hh) {
    const char* asrc = (const char*)g_h1f;
    uint32_t sz = 0;
    if (nbr >= 0) { asrc += (size_t)nbr*256 + ch*128 + hh*64; sz = 16; }
    uint32_t adst = Ab + row*(AST*4) + hh*64;
    #pragma unroll
    for (int j = 0; j < 4; j++) cp16(adst + j*16, asrc + j*16, sz);
    const char* bsrc = (const char*)g_wct + (size_t)(tap*128 + row)*512 + ch*256 + hh*128;
    uint32_t bdst = Bb + row*(BST*4) + hh*128;
    #pragma unroll
    for (int j = 0; j < 8; j++) cp16(bdst + j*16, bsrc + j*16, 16);
}

__global__ __launch_bounds__(256, 1) void conv_kernel(
    const float* __restrict__ xf, const float* __restrict__ nrm, const int* __restrict__ xidx) {
    extern __shared__ uint8_t smemraw[];
    const uint32_t sb32 = smem_u32(smemraw);
    const int tid = threadIdx.x, warp = tid >> 5, lane = tid & 31;
    const int wm = warp >> 1, wn = warp & 1;
    const int lq = lane >> 2, lr = lane & 3;
    const int base = blockIdx.x * 128;
    const int row = tid >> 1, hh = tid & 1;

    const int n0i = base + row;
    const int myb = xidx[3*n0i] << 16, myy = xidx[3*n0i+1], myx = xidx[3*n0i+2];

    float acc[2][8][4];
    #pragma unroll
    for (int mt = 0; mt < 2; mt++)
        #pragma unroll
        for (int nj = 0; nj < 8; nj++)
            #pragma unroll
            for (int q = 0; q < 4; q++) acc[mt][nj][q] = 0.0f;

    const uint32_t AbU[2] = { sb32, sb32 + BUFB };
    const uint32_t BbU[2] = { sb32 + ACHUNK, sb32 + BUFB + ACHUNK };

    int nbr_s = nbr_lookup(myb, myy, myx, 0);
    int nbr_p = -1;
    stage_chunk(AbU[0], BbU[0], 0, 0, nbr_s, row, hh);
    CP_COMMIT();

    #pragma unroll 2
    for (int c = 0; c < 98; c++) {
        const int tap = c >> 1;
        if (c < 97) {
            const int c1 = c + 1;
            int nbr_use = (c1 & 1) ? nbr_s : nbr_p;
            if ((c1 & 1) == 0) nbr_s = nbr_p;
            stage_chunk(AbU[c1 & 1], BbU[c1 & 1], c1 >> 1, c1 & 1, nbr_use, row, hh);
            CP_COMMIT();
            CP_WAIT1();
        } else {
            CP_WAIT0();
        }
        __syncthreads();
        if ((c & 1) == 0 && tap + 1 < 49)
            nbr_p = nbr_lookup(myb, myy, myx, tap + 1);

        const uint32_t* As = (const uint32_t*)(smemraw + (c & 1) * BUFB);
        const uint32_t* Bs = (const uint32_t*)(smemraw + (c & 1) * BUFB + ACHUNK);
        #pragma unroll
        for (int ks = 0; ks < 4; ks++) {
            uint32_t a[2][4];
            #pragma unroll
            for (int mt = 0; mt < 2; mt++) {
                const uint32_t* ap = As + (wm*32 + mt*16 + lq)*AST + ks*8 + lr;
                a[mt][0] = ap[0];
                a[mt][1] = ap[8*AST];
                a[mt][2] = ap[4];
                a[mt][3] = ap[8*AST + 4];
            }
            #pragma unroll
            for (int nj = 0; nj < 8; nj++) {
                const uint32_t* bp = Bs + (wn*64 + nj*8 + lq)*BST + (ks*8 + lr)*2;
                uint2 u0 = *(const uint2*)(bp);
                uint2 u1 = *(const uint2*)(bp + 8);
                uint32_t bh[2] = {u0.x, u1.x}, bl[2] = {u0.y, u1.y};
                #pragma unroll
                for (int mt = 0; mt < 2; mt++) {
                    mma_f16(acc[mt][nj], a[mt], bh);
                    mma_f16(acc[mt][nj], a[mt], bl);
                }
            }
        }
        __syncthreads();
    }

    #pragma unroll
    for (int mt = 0; mt < 2; mt++) {
        int m = wm*32 + mt*16 + lq;
        float inv0 = 1.0f / nrm[base + m];
        float inv8 = 1.0f / nrm[base + m + 8];
        #pragma unroll
        for (int nj = 0; nj < 8; nj++) {
            int nn = wn*64 + nj*8 + lr*2;
            int gm = base + m;
            float2 x0 = *(const float2*)(xf + (size_t)gm*C + nn);
            float2 o0 = { x0.x + acc[mt][nj][0]*inv0, x0.y + acc[mt][nj][1]*inv0 };
            *(float2*)(g_x + (size_t)gm*C + nn) = o0;
            gm += 8;
            float2 x1 = *(const float2*)(xf + (size_t)gm*C + nn);
            float2 o1 = { x1.x + acc[mt][nj][2]*inv8, x1.y + acc[mt][nj][3]*inv8 };
            *(float2*)(g_x + (size_t)gm*C + nn) = o1;
        }
    }
}

// ---------------- launch 5: LN2 + modulation + MLP (2-pass fp16) + residual ---------
#define AST2 68                              // FIXED: 64 data words (C=128 fp16) + 4 pad
#define HST  132
#define MLP_SMEM ((64*AST2 + 64*HST) * 4)    // 51200 B
__global__ __launch_bounds__(256) void mlp_kernel(
    const float* __restrict__ lnw, const float* __restrict__ lnb,
    const float* __restrict__ b1,  const float* __restrict__ b2, float* __restrict__ out) {
    extern __shared__ uint32_t smem[];
    uint32_t* As = smem;
    uint32_t* Hs = smem + 64 * AST2;
    const int tid = threadIdx.x, warp = tid >> 5, lane = tid & 31;
    const int lq = lane >> 2, lr = lane & 3;
    const int base = blockIdx.x * 64;

    #pragma unroll
    for (int rr = 0; rr < 8; rr++) {
        int rl = warp*8 + rr, n = base + rl, b = n >> 15;
        float4 v = *(const float4*)(g_x + (size_t)n*C + lane*4);
        float s = v.x+v.y+v.z+v.w, sq = v.x*v.x+v.y*v.y+v.z*v.z+v.w*v.w;
        #pragma unroll
        for (int o = 16; o; o >>= 1) {
            s  += __shfl_xor_sync(0xffffffffu, s,  o);
            sq += __shfl_xor_sync(0xffffffffu, sq, o);
        }
        float mu = s*(1.0f/C), rs = rsqrtf(sq*(1.0f/C) - mu*mu + LN_EPS);
        float vv[4] = {v.x,v.y,v.z,v.w}, o4[4];
        #pragma unroll
        for (int u = 0; u < 4; u++) {
            int c = lane*4 + u;
            float f = (vv[u]-mu)*rs*lnw[c] + lnb[c];
            f = f*(1.0f + g_tt2[b*256+c]) + g_tt2[b*256+128+c];
            o4[u] = f*(1.0f + g_zz2[b*128+c]);
        }
        uint2 pk = { pack_h2(o4[0], o4[1]), pack_h2(o4[2], o4[3]) };
        *(uint2*)(As + rl*AST2 + lane*2) = pk;
    }
    __syncthreads();

    // GEMM1: H = gelu(A @ w1 + b1); warp covers n in [warp*32, warp*32+32)
    float acc1[4][4][4];
    #pragma unroll
    for (int mt = 0; mt < 4; mt++)
        #pragma unroll
        for (int nj = 0; nj < 4; nj++)
            #pragma unroll
            for (int q = 0; q < 4; q++) acc1[mt][nj][q] = 0.0f;
    #pragma unroll
    for (int ks = 0; ks < 8; ks++) {
        uint32_t a[4][4];
        #pragma unroll
        for (int mt = 0; mt < 4; mt++) {
            const uint32_t* ap = As + (mt*16 + lq)*AST2 + ks*8 + lr;
            a[mt][0] = ap[0]; a[mt][1] = ap[8*AST2]; a[mt][2] = ap[4]; a[mt][3] = ap[8*AST2 + 4];
        }
        #pragma unroll
        for (int nj = 0; nj < 4; nj++) {
            const uint32_t* bp = g_w1t + (warp*32 + nj*8 + lq)*128 + (ks*8 + lr)*2;
            uint2 u0 = *(const uint2*)(bp), u1 = *(const uint2*)(bp + 8);
            uint32_t bh[2] = {u0.x, u1.x}, bl[2] = {u0.y, u1.y};
            #pragma unroll
            for (int mt = 0; mt < 4; mt++) {
                mma_f16(acc1[mt][nj], a[mt], bh);
                mma_f16(acc1[mt][nj], a[mt], bl);
            }
        }
    }
    #pragma unroll
    for (int nj = 0; nj < 4; nj++) {
        int nn = warp*32 + nj*8 + lr*2;
        float2 bb = *(const float2*)(b1 + nn);
        int wrd = warp*16 + nj*4 + lr;
        #pragma unroll
        for (int mt = 0; mt < 4; mt++) {
            int m0 = mt*16 + lq;
            Hs[m0*HST + wrd]     = pack_h2(gelu_exact(acc1[mt][nj][0]+bb.x), gelu_exact(acc1[mt][nj][1]+bb.y));
            Hs[(m0+8)*HST + wrd] = pack_h2(gelu_exact(acc1[mt][nj][2]+bb.x), gelu_exact(acc1[mt][nj][3]+bb.y));
        }
    }
    __syncthreads();

    // GEMM2: out = x + H @ w2 + b2; warp covers n in [warp*16, warp*16+16); K=256
    float acc2[4][2][4];
    #pragma unroll
    for (int mt = 0; mt < 4; mt++)
        #pragma unroll
        for (int nj = 0; nj < 2; nj++)
            #pragma unroll
            for (int q = 0; q < 4; q++) acc2[mt][nj][q] = 0.0f;
    #pragma unroll
    for (int ks = 0; ks < 16; ks++) {
        uint32_t a[4][4];
        #pragma unroll
        for (int mt = 0; mt < 4; mt++) {
            const uint32_t* ap = Hs + (mt*16 + lq)*HST + ks*8 + lr;
            a[mt][0] = ap[0]; a[mt][1] = ap[8*HST]; a[mt][2] = ap[4]; a[mt][3] = ap[8*HST + 4];
        }
        #pragma unroll
        for (int nj = 0; nj < 2; nj++) {
            const uint32_t* bp = g_w2t + (warp*16 + nj*8 + lq)*256 + (ks*8 + lr)*2;
            uint2 u0 = *(const uint2*)(bp), u1 = *(const uint2*)(bp + 8);
            uint32_t bh[2] = {u0.x, u1.x}, bl[2] = {u0.y, u1.y};
            #pragma unroll
            for (int mt = 0; mt < 4; mt++) {
                mma_f16(acc2[mt][nj], a[mt], bh);
                mma_f16(acc2[mt][nj], a[mt], bl);
            }
        }
    }
    #pragma unroll
    for (int nj = 0; nj < 2; nj++) {
        int nn = warp*16 + nj*8 + lr*2;
        float2 bb = *(const float2*)(b2 + nn);
        #pragma unroll
        for (int mt = 0; mt < 4; mt++) {
            int m0 = mt*16 + lq;
            int gm = base + m0;
            float2 x = *(const float2*)(g_x + (size_t)gm*C + nn);
            float2 o = { x.x + acc2[mt][nj][0] + bb.x, x.y + acc2[mt][nj][1] + bb.y };
            *(float2*)(out + (size_t)gm*C + nn) = o;
            gm += 8;
            x = *(const float2*)(g_x + (size_t)gm*C + nn);
            o.x = x.x + acc2[mt][nj][2] + bb.x;
            o.y = x.y + acc2[mt][nj][3] + bb.y;
            *(float2*)(out + (size_t)gm*C + nn) = o;
        }
    }
}

extern "C" void kernel_launch(void* const* d_in, const int* in_sizes, int n_in,
                              void* d_out, int out_size) {
    const float* xf    = (const float*)d_in[0];
    const int*   xi    = (const int*)  d_in[1];
    const float* t     = (const float*)d_in[2];
    const float* z     = (const float*)d_in[3];
    const float* nrm   = (const float*)d_in[4];
    const float* ln1w  = (const float*)d_in[5];
    const float* ln1b  = (const float*)d_in[6];
    const float* ln2w  = (const float*)d_in[7];
    const float* ln2b  = (const float*)d_in[8];
    const float* convw = (const float*)d_in[9];
    const float* t1w   = (const float*)d_in[10];
    const float* t1b   = (const float*)d_in[11];
    const float* t2w   = (const float*)d_in[12];
    const float* t2b   = (const float*)d_in[13];
    const float* z1w1  = (const float*)d_in[14];
    const float* z1b1  = (const float*)d_in[15];
    const float* z1w2  = (const float*)d_in[16];
    const float* z1b2  = (const float*)d_in[17];
    const float* z2w1  = (const float*)d_in[18];
    const float* z2b1  = (const float*)d_in[19];
    const float* z2w2  = (const float*)d_in[20];
    const float* z2b2  = (const float*)d_in[21];
    const float* w1    = (const float*)d_in[22];
    const float* b1    = (const float*)d_in[23];
    const float* w2    = (const float*)d_in[24];
    const float* b2    = (const float*)d_in[25];
    float* out = (float*)d_out;

    cudaFuncSetAttribute(conv_kernel, cudaFuncAttributeMaxDynamicSharedMemorySize, CONV_SMEM);
    cudaFuncSetAttribute(mlp_kernel,  cudaFuncAttributeMaxDynamicSharedMemorySize, MLP_SMEM);

    fill_grid_kernel<<<(NBATCH*IMG*IMG)/256, 256>>>();
    fused_init_kernel<<<512 + 8 + SPLIT_BLKS, 256>>>(xi, t, z, t1w, t1b, t2w, t2b,
        z1w1, z1b1, z1w2, z1b2, z2w1, z2b1, z2w2, z2b2, convw, w1, w2);
    modulate1_kernel<<<NPTS/8, 256>>>(xf, ln1w, ln1b);
    conv_kernel<<<NPTS/128, 256, CONV_SMEM>>>(xf, nrm, xi);
    mlp_kernel<<<NPTS/64, 256, MLP_SMEM>>>(ln2w, ln2b, b1, b2, out);
    (void)in_sizes; (void)n_in; (void)out_size;
}

// round 9
// speedup vs baseline: 4.8738x; 2.0935x over previous
#include <cuda_runtime.h>
#include <cuda_fp16.h>
#include <math.h>
#include <stdint.h>

#define NBATCH 4
#define IMG    256
#define C      128
#define ACTPTS 32768
#define NPTS   (NBATCH*ACTPTS)
#define TD     512
#define ZD     256
#define LN_EPS 1e-5f

__device__ uint32_t g_h1f[(size_t)NPTS * 64];    // modulated input, fp16x2 words (32 MB)
__device__ float    g_x [(size_t)NPTS * C];
__device__ int      g_grid[NBATCH * IMG * IMG];
__device__ float g_tt1[NBATCH*2*C], g_tt2[NBATCH*2*C], g_zz1[NBATCH*C], g_zz2[NBATCH*C];
__device__ uint32_t g_wct[49 * 128 * 64];        // conv w^T fp16x2: [tap][cout][64 words]
__device__ uint32_t g_w1t[256 * 64];             // w1^T fp16x2: [n][64 words] (K=128)
__device__ uint32_t g_w2t[128 * 128];            // w2^T fp16x2: [n][128 words] (K=256)

__device__ __forceinline__ float gelu_exact(float x) {
    return 0.5f * x * (1.0f + erff(x * 0.70710678118654752440f));
}
__device__ __forceinline__ uint32_t pack_h2(float a, float b) {
    __half2 h = __floats2half2_rn(a, b);
    return *(uint32_t*)&h;
}
__device__ __forceinline__ void mma_f16(float* d, const uint32_t* a, const uint32_t* b) {
    asm volatile("mma.sync.aligned.m16n8k16.row.col.f32.f16.f16.f32 "
        "{%0,%1,%2,%3},{%4,%5,%6,%7},{%8,%9},{%0,%1,%2,%3};\n"
        : "+f"(d[0]), "+f"(d[1]), "+f"(d[2]), "+f"(d[3])
        : "r"(a[0]), "r"(a[1]), "r"(a[2]), "r"(a[3]), "r"(b[0]), "r"(b[1]));
}
__device__ __forceinline__ uint32_t smem_u32(const void* p) {
    uint32_t a;
    asm("{ .reg .u64 t; cvta.to.shared.u64 t, %1; cvt.u32.u64 %0, t; }" : "=r"(a) : "l"(p));
    return a;
}
__device__ __forceinline__ void cp16(uint32_t dst, const void* src, uint32_t srcsize) {
    asm volatile("cp.async.ca.shared.global [%0], [%1], 16, %2;"
                 :: "r"(dst), "l"(src), "r"(srcsize) : "memory");
}
#define CP_COMMIT() asm volatile("cp.async.commit_group;" ::: "memory")
#define CP_WAIT1()  asm volatile("cp.async.wait_group 1;" ::: "memory")
#define CP_WAIT0()  asm volatile("cp.async.wait_group 0;" ::: "memory")

// ---------------- launch 1: grid fill ----------------
__global__ void fill_grid_kernel() { g_grid[blockIdx.x * 256 + threadIdx.x] = -1; }

// ---------------- launch 2: fused init (scatter + modvec + fp16 weight pack) --------
#define NCONVW (49*128*64)
#define NW1W   (256*64)
#define NW2W   (128*128)
#define SPLIT_BLKS ((NCONVW + NW1W + NW2W) / 256)   // 1696
__global__ void fused_init_kernel(
    const int* __restrict__ xidx,
    const float* __restrict__ t,   const float* __restrict__ z,
    const float* __restrict__ t1w, const float* __restrict__ t1b,
    const float* __restrict__ t2w, const float* __restrict__ t2b,
    const float* __restrict__ z1w1, const float* __restrict__ z1b1,
    const float* __restrict__ z1w2, const float* __restrict__ z1b2,
    const float* __restrict__ z2w1, const float* __restrict__ z2b1,
    const float* __restrict__ z2w2, const float* __restrict__ z2b2,
    const float* __restrict__ convw, const float* __restrict__ w1, const float* __restrict__ w2)
{
    const int bid = blockIdx.x, tid = threadIdx.x;
    __shared__ float sbuf[768];
    if (bid < 512) {                       // scatter
        int n = bid * 256 + tid;
        g_grid[(xidx[3*n] << 16) | (xidx[3*n+1] << 8) | xidx[3*n+2]] = n;
    } else if (bid < 520) {                // modvec
        const int b = (bid - 512) >> 1;
        if (((bid - 512) & 1) == 0) {
            float* gt = sbuf;
            gt[tid] = gelu_exact(t[b*TD + tid]);
            gt[tid + 256] = gelu_exact(t[b*TD + tid + 256]);
            __syncthreads();
            float a1 = t1b[tid], a2 = t2b[tid];
            #pragma unroll 8
            for (int k = 0; k < TD; k++) { float g = gt[k]; a1 += g*t1w[k*256+tid]; a2 += g*t2w[k*256+tid]; }
            g_tt1[b*256 + tid] = a1; g_tt2[b*256 + tid] = a2;
        } else {
            float* gz = sbuf; float* hz = sbuf + 256;
            gz[tid] = z[b*ZD + tid];
            __syncthreads();
            {
                int j = tid & 127;
                const float* w = (tid < 128) ? z1w1 : z2w1;
                const float* bb = (tid < 128) ? z1b1 : z2b1;
                float a = bb[j];
                #pragma unroll 8
                for (int k = 0; k < ZD; k++) a += gz[k] * w[k*C + j];
                hz[tid] = gelu_exact(a);
            }
            __syncthreads();
            {
                int j = tid & 127;
                const float* w = (tid < 128) ? z1w2 : z2w2;
                const float* bb = (tid < 128) ? z1b2 : z2b2;
                const float* h = (tid < 128) ? hz : (hz + C);
                float a = bb[j];
                #pragma unroll 8
                for (int k = 0; k < C; k++) a += h[k] * w[k*C + j];
                if (tid < 128) g_zz1[b*C + j] = a; else g_zz2[b*C + j] = a;
            }
        }
    } else {                               // fp16 weight pack (single plane)
        int i = (bid - 520) * 256 + tid;
        if (i < NCONVW) {
            int p = i & 63, rest = i >> 6;
            int cout = rest & 127, tap = rest >> 7;
            g_wct[(tap*128 + cout)*64 + p] =
                pack_h2(convw[(tap*128 + 2*p + 0)*128 + cout], convw[(tap*128 + 2*p + 1)*128 + cout]);
        } else if (i < NCONVW + NW1W) {
            int j = i - NCONVW, p = j & 63, n = j >> 6;
            g_w1t[n*64 + p] = pack_h2(w1[(2*p+0)*256 + n], w1[(2*p+1)*256 + n]);
        } else {
            int j = i - (NCONVW + NW1W), p = j & 127, n = j >> 7;
            g_w2t[n*128 + p] = pack_h2(w2[(2*p+0)*128 + n], w2[(2*p+1)*128 + n]);
        }
    }
}

// ---------------- launch 3: LN1 + modulation -> fp16 plane ----------------
__global__ void modulate1_kernel(const float* __restrict__ xf,
                                 const float* __restrict__ lnw, const float* __restrict__ lnb) {
    const int warp = threadIdx.x >> 5, lane = threadIdx.x & 31;
    const int n = blockIdx.x * 8 + warp, b = n >> 15;
    float4 v = *(const float4*)(xf + (size_t)n*C + lane*4);
    float s = v.x + v.y + v.z + v.w;
    float sq = v.x*v.x + v.y*v.y + v.z*v.z + v.w*v.w;
    #pragma unroll
    for (int o = 16; o; o >>= 1) {
        s  += __shfl_xor_sync(0xffffffffu, s,  o);
        sq += __shfl_xor_sync(0xffffffffu, sq, o);
    }
    float mu = s * (1.0f/C);
    float rs = rsqrtf(sq*(1.0f/C) - mu*mu + LN_EPS);
    float vv[4] = {v.x, v.y, v.z, v.w}, o4[4];
    #pragma unroll
    for (int u = 0; u < 4; u++) {
        int c = lane*4 + u;
        float f = (vv[u] - mu)*rs*lnw[c] + lnb[c];
        f = f*(1.0f + g_tt1[b*256 + c]) + g_tt1[b*256 + 128 + c];
        o4[u] = f*(1.0f + g_zz1[b*128 + c]);
    }
    uint2 pk = { pack_h2(o4[0], o4[1]), pack_h2(o4[2], o4[3]) };
    *(uint2*)(g_h1f + (size_t)n*64 + lane*2) = pk;
}

// ---------------- launch 4: conv (pure fp16, cp.async double-buffer) ----------------
#define AST 36                           // A chunk row stride (words); 32 data
#define ACHUNK (128*AST*4)               // 18432 B
#define BST 36                           // B chunk row stride (words); 32 data
#define BCHUNK (128*BST*4)               // 18432 B
#define BUFB (ACHUNK + BCHUNK)           // 36864 B
#define CONV_SMEM (2*BUFB)               // 73728 B -> 2 CTAs/SM
__device__ __forceinline__ int nbr_lookup(int myb, int myy, int myx, int tap) {
    int ny = myy + tap/7 - 3, nx = myx + tap%7 - 3;
    if ((unsigned)ny < 256u && (unsigned)nx < 256u) return g_grid[myb | (ny<<8) | nx];
    return -1;
}
__device__ __forceinline__ void stage_chunk(uint32_t Ab, uint32_t Bb, int tap, int ch,
                                            int nbr, int row, int hh) {
    const char* asrc = (const char*)g_h1f;
    uint32_t sz = 0;
    if (nbr >= 0) { asrc += (size_t)nbr*256 + ch*128 + hh*64; sz = 16; }
    uint32_t adst = Ab + row*(AST*4) + hh*64;
    #pragma unroll
    for (int j = 0; j < 4; j++) cp16(adst + j*16, asrc + j*16, sz);
    const char* bsrc = (const char*)g_wct + (size_t)(tap*128 + row)*256 + ch*128 + hh*64;
    uint32_t bdst = Bb + row*(BST*4) + hh*64;
    #pragma unroll
    for (int j = 0; j < 4; j++) cp16(bdst + j*16, bsrc + j*16, 16);
}

__global__ __launch_bounds__(256, 2) void conv_kernel(
    const float* __restrict__ xf, const float* __restrict__ nrm, const int* __restrict__ xidx) {
    extern __shared__ uint8_t smemraw[];
    const uint32_t sb32 = smem_u32(smemraw);
    const int tid = threadIdx.x, warp = tid >> 5, lane = tid & 31;
    const int wm = warp >> 1, wn = warp & 1;
    const int lq = lane >> 2, lr = lane & 3;
    const int base = blockIdx.x * 128;
    const int row = tid >> 1, hh = tid & 1;

    const int n0i = base + row;
    const int myb = xidx[3*n0i] << 16, myy = xidx[3*n0i+1], myx = xidx[3*n0i+2];

    float acc[2][8][4];
    #pragma unroll
    for (int mt = 0; mt < 2; mt++)
        #pragma unroll
        for (int nj = 0; nj < 8; nj++)
            #pragma unroll
            for (int q = 0; q < 4; q++) acc[mt][nj][q] = 0.0f;

    const uint32_t AbU[2] = { sb32, sb32 + BUFB };
    const uint32_t BbU[2] = { sb32 + ACHUNK, sb32 + BUFB + ACHUNK };

    int nbr_s = nbr_lookup(myb, myy, myx, 0);
    int nbr_p = -1;
    stage_chunk(AbU[0], BbU[0], 0, 0, nbr_s, row, hh);
    CP_COMMIT();

    #pragma unroll 2
    for (int c = 0; c < 98; c++) {
        const int tap = c >> 1;
        if (c < 97) {
            const int c1 = c + 1;
            int nbr_use = (c1 & 1) ? nbr_s : nbr_p;
            if ((c1 & 1) == 0) nbr_s = nbr_p;
            stage_chunk(AbU[c1 & 1], BbU[c1 & 1], c1 >> 1, c1 & 1, nbr_use, row, hh);
            CP_COMMIT();
            CP_WAIT1();
        } else {
            CP_WAIT0();
        }
        __syncthreads();
        if ((c & 1) == 0 && tap + 1 < 49)
            nbr_p = nbr_lookup(myb, myy, myx, tap + 1);

        const uint32_t* As = (const uint32_t*)(smemraw + (c & 1) * BUFB);
        const uint32_t* Bs = (const uint32_t*)(smemraw + (c & 1) * BUFB + ACHUNK);
        #pragma unroll
        for (int ks = 0; ks < 4; ks++) {
            uint32_t a[2][4];
            #pragma unroll
            for (int mt = 0; mt < 2; mt++) {
                const uint32_t* ap = As + (wm*32 + mt*16 + lq)*AST + ks*8 + lr;
                a[mt][0] = ap[0];
                a[mt][1] = ap[8*AST];
                a[mt][2] = ap[4];
                a[mt][3] = ap[8*AST + 4];
            }
            #pragma unroll
            for (int nj = 0; nj < 8; nj++) {
                const uint32_t* bp = Bs + (wn*64 + nj*8 + lq)*BST + ks*8 + lr;
                uint32_t b[2] = { bp[0], bp[4] };
                #pragma unroll
                for (int mt = 0; mt < 2; mt++)
                    mma_f16(acc[mt][nj], a[mt], b);
            }
        }
        __syncthreads();
    }

    #pragma unroll
    for (int mt = 0; mt < 2; mt++) {
        int m = wm*32 + mt*16 + lq;
        float inv0 = 1.0f / nrm[base + m];
        float inv8 = 1.0f / nrm[base + m + 8];
        #pragma unroll
        for (int nj = 0; nj < 8; nj++) {
            int nn = wn*64 + nj*8 + lr*2;
            int gm = base + m;
            float2 x0 = *(const float2*)(xf + (size_t)gm*C + nn);
            float2 o0 = { x0.x + acc[mt][nj][0]*inv0, x0.y + acc[mt][nj][1]*inv0 };
            *(float2*)(g_x + (size_t)gm*C + nn) = o0;
            gm += 8;
            float2 x1 = *(const float2*)(xf + (size_t)gm*C + nn);
            float2 o1 = { x1.x + acc[mt][nj][2]*inv8, x1.y + acc[mt][nj][3]*inv8 };
            *(float2*)(g_x + (size_t)gm*C + nn) = o1;
        }
    }
}

// ---------------- launch 5: LN2 + modulation + MLP (pure fp16) + residual -----------
#define AST2 68                              // 64 data words (C=128 fp16) + 4 pad
#define HST  132                             // 128 data words (HID=256 fp16) + 4 pad
#define MLP_SMEM ((64*AST2 + 64*HST) * 4)    // 51200 B
__global__ __launch_bounds__(256) void mlp_kernel(
    const float* __restrict__ lnw, const float* __restrict__ lnb,
    const float* __restrict__ b1,  const float* __restrict__ b2, float* __restrict__ out) {
    extern __shared__ uint32_t smem[];
    uint32_t* As = smem;
    uint32_t* Hs = smem + 64 * AST2;
    const int tid = threadIdx.x, warp = tid >> 5, lane = tid & 31;
    const int lq = lane >> 2, lr = lane & 3;
    const int base = blockIdx.x * 64;

    #pragma unroll
    for (int rr = 0; rr < 8; rr++) {
        int rl = warp*8 + rr, n = base + rl, b = n >> 15;
        float4 v = *(const float4*)(g_x + (size_t)n*C + lane*4);
        float s = v.x+v.y+v.z+v.w, sq = v.x*v.x+v.y*v.y+v.z*v.z+v.w*v.w;
        #pragma unroll
        for (int o = 16; o; o >>= 1) {
            s  += __shfl_xor_sync(0xffffffffu, s,  o);
            sq += __shfl_xor_sync(0xffffffffu, sq, o);
        }
        float mu = s*(1.0f/C), rs = rsqrtf(sq*(1.0f/C) - mu*mu + LN_EPS);
        float vv[4] = {v.x,v.y,v.z,v.w}, o4[4];
        #pragma unroll
        for (int u = 0; u < 4; u++) {
            int c = lane*4 + u;
            float f = (vv[u]-mu)*rs*lnw[c] + lnb[c];
            f = f*(1.0f + g_tt2[b*256+c]) + g_tt2[b*256+128+c];
            o4[u] = f*(1.0f + g_zz2[b*128+c]);
        }
        uint2 pk = { pack_h2(o4[0], o4[1]), pack_h2(o4[2], o4[3]) };
        *(uint2*)(As + rl*AST2 + lane*2) = pk;
    }
    __syncthreads();

    // GEMM1: H = gelu(A @ w1 + b1); warp covers n in [warp*32, warp*32+32)
    float acc1[4][4][4];
    #pragma unroll
    for (int mt = 0; mt < 4; mt++)
        #pragma unroll
        for (int nj = 0; nj < 4; nj++)
            #pragma unroll
            for (int q = 0; q < 4; q++) acc1[mt][nj][q] = 0.0f;
    #pragma unroll
    for (int ks = 0; ks < 8; ks++) {
        uint32_t a[4][4];
        #pragma unroll
        for (int mt = 0; mt < 4; mt++) {
            const uint32_t* ap = As + (mt*16 + lq)*AST2 + ks*8 + lr;
            a[mt][0] = ap[0]; a[mt][1] = ap[8*AST2]; a[mt][2] = ap[4]; a[mt][3] = ap[8*AST2 + 4];
        }
        #pragma unroll
        for (int nj = 0; nj < 4; nj++) {
            const uint32_t* bp = g_w1t + (warp*32 + nj*8 + lq)*64 + ks*8 + lr;
            uint32_t b[2] = { bp[0], bp[4] };
            #pragma unroll
            for (int mt = 0; mt < 4; mt++)
                mma_f16(acc1[mt][nj], a[mt], b);
        }
    }
    #pragma unroll
    for (int nj = 0; nj < 4; nj++) {
        int nn = warp*32 + nj*8 + lr*2;
        float2 bb = *(const float2*)(b1 + nn);
        int wrd = warp*16 + nj*4 + lr;
        #pragma unroll
        for (int mt = 0; mt < 4; mt++) {
            int m0 = mt*16 + lq;
            Hs[m0*HST + wrd]     = pack_h2(gelu_exact(acc1[mt][nj][0]+bb.x), gelu_exact(acc1[mt][nj][1]+bb.y));
            Hs[(m0+8)*HST + wrd] = pack_h2(gelu_exact(acc1[mt][nj][2]+bb.x), gelu_exact(acc1[mt][nj][3]+bb.y));
        }
    }
    __syncthreads();

    // GEMM2: out = x + H @ w2 + b2; warp covers n in [warp*16, warp*16+16); K=256
    float acc2[4][2][4];
    #pragma unroll
    for (int mt = 0; mt < 4; mt++)
        #pragma unroll
        for (int nj = 0; nj < 2; nj++)
            #pragma unroll
            for (int q = 0; q < 4; q++) acc2[mt][nj][q] = 0.0f;
    #pragma unroll
    for (int ks = 0; ks < 16; ks++) {
        uint32_t a[4][4];
        #pragma unroll
        for (int mt = 0; mt < 4; mt++) {
            const uint32_t* ap = Hs + (mt*16 + lq)*HST + ks*8 + lr;
            a[mt][0] = ap[0]; a[mt][1] = ap[8*HST]; a[mt][2] = ap[4]; a[mt][3] = ap[8*HST + 4];
        }
        #pragma unroll
        for (int nj = 0; nj < 2; nj++) {
            const uint32_t* bp = g_w2t + (warp*16 + nj*8 + lq)*128 + ks*8 + lr;
            uint32_t b[2] = { bp[0], bp[4] };
            #pragma unroll
            for (int mt = 0; mt < 4; mt++)
                mma_f16(acc2[mt][nj], a[mt], b);
        }
    }
    #pragma unroll
    for (int nj = 0; nj < 2; nj++) {
        int nn = warp*16 + nj*8 + lr*2;
        float2 bb = *(const float2*)(b2 + nn);
        #pragma unroll
        for (int mt = 0; mt < 4; mt++) {
            int m0 = mt*16 + lq;
            int gm = base + m0;
            float2 x = *(const float2*)(g_x + (size_t)gm*C + nn);
            float2 o = { x.x + acc2[mt][nj][0] + bb.x, x.y + acc2[mt][nj][1] + bb.y };
            *(float2*)(out + (size_t)gm*C + nn) = o;
            gm += 8;
            x = *(const float2*)(g_x + (size_t)gm*C + nn);
            o.x = x.x + acc2[mt][nj][2] + bb.x;
            o.y = x.y + acc2[mt][nj][3] + bb.y;
            *(float2*)(out + (size_t)gm*C + nn) = o;
        }
    }
}

extern "C" void kernel_launch(void* const* d_in, const int* in_sizes, int n_in,
                              void* d_out, int out_size) {
    const float* xf    = (const float*)d_in[0];
    const int*   xi    = (const int*)  d_in[1];
    const float* t     = (const float*)d_in[2];
    const float* z     = (const float*)d_in[3];
    const float* nrm   = (const float*)d_in[4];
    const float* ln1w  = (const float*)d_in[5];
    const float* ln1b  = (const float*)d_in[6];
    const float* ln2w  = (const float*)d_in[7];
    const float* ln2b  = (const float*)d_in[8];
    const float* convw = (const float*)d_in[9];
    const float* t1w   = (const float*)d_in[10];
    const float* t1b   = (const float*)d_in[11];
    const float* t2w   = (const float*)d_in[12];
    const float* t2b   = (const float*)d_in[13];
    const float* z1w1  = (const float*)d_in[14];
    const float* z1b1  = (const float*)d_in[15];
    const float* z1w2  = (const float*)d_in[16];
    const float* z1b2  = (const float*)d_in[17];
    const float* z2w1  = (const float*)d_in[18];
    const float* z2b1  = (const float*)d_in[19];
    const float* z2w2  = (const float*)d_in[20];
    const float* z2b2  = (const float*)d_in[21];
    const float* w1    = (const float*)d_in[22];
    const float* b1    = (const float*)d_in[23];
    const float* w2    = (const float*)d_in[24];
    const float* b2    = (const float*)d_in[25];
    float* out = (float*)d_out;

    cudaFuncSetAttribute(conv_kernel, cudaFuncAttributeMaxDynamicSharedMemorySize, CONV_SMEM);
    cudaFuncSetAttribute(mlp_kernel,  cudaFuncAttributeMaxDynamicSharedMemorySize, MLP_SMEM);

    fill_grid_kernel<<<(NBATCH*IMG*IMG)/256, 256>>>();
    fused_init_kernel<<<512 + 8 + SPLIT_BLKS, 256>>>(xi, t, z, t1w, t1b, t2w, t2b,
        z1w1, z1b1, z1w2, z1b2, z2w1, z2b1, z2w2, z2b2, convw, w1, w2);
    modulate1_kernel<<<NPTS/8, 256>>>(xf, ln1w, ln1b);
    conv_kernel<<<NPTS/128, 256, CONV_SMEM>>>(xf, nrm, xi);
    mlp_kernel<<<NPTS/64, 256, MLP_SMEM>>>(ln2w, ln2b, b1, b2, out);
    (void)in_sizes; (void)n_in; (void)out_size;
}